// round 6
// baseline (speedup 1.0000x reference)
#include <cuda_runtime.h>
#include <math.h>

#define B_ 64
#define L_ 512
#define E_ 64
#define H_ 8
#define D_ 8
#define ROWS (B_*L_)          // 32768
#define QK_SCALE 0.35355339059327373f   // 1/sqrt(8)
#define LOG2E_F  1.4426950408889634f
#define NSL 4                 // key slices
#define SLK (L_/NSL)          // 128 keys per slice

typedef unsigned long long u64t;

// ---- packed f32x2 helpers (ptxas never auto-fuses; PTX only) ----
__device__ __forceinline__ u64t fma2(u64t a, u64t b, u64t c) {
    u64t d; asm("fma.rn.f32x2 %0, %1, %2, %3;" : "=l"(d) : "l"(a), "l"(b), "l"(c)); return d;
}
__device__ __forceinline__ u64t mul2(u64t a, u64t b) {
    u64t d; asm("mul.rn.f32x2 %0, %1, %2;" : "=l"(d) : "l"(a), "l"(b)); return d;
}
__device__ __forceinline__ u64t pack2(float lo, float hi) {
    u64t d; asm("mov.b64 %0, {%1, %2};" : "=l"(d) : "f"(lo), "f"(hi)); return d;
}
__device__ __forceinline__ void unpack2(u64t a, float& lo, float& hi) {
    asm("mov.b64 {%0, %1}, %2;" : "=f"(lo), "=f"(hi) : "l"(a));
}
__device__ __forceinline__ float ex2f(float x) {
    float r; asm("ex2.approx.f32 %0, %1;" : "=f"(r) : "f"(x)); return r;
}
__device__ __forceinline__ float lg2f(float x) {
    float r; asm("lg2.approx.f32 %0, %1;" : "=f"(r) : "f"(x)); return r;
}

// ---- scratch (static device arrays; no allocation) ----
__device__ float g_qh  [ROWS*E_];
__device__ float g_kh  [ROWS*E_];
__device__ float g_vh  [ROWS*E_];
__device__ float g_ctx [ROWS*E_];
__device__ float g_t0  [ROWS*E_];
__device__ float g_x   [ROWS*E_];
__device__ float g_f1  [ROWS*E_];
__device__ float g_p1  [ROWS*NSL*H_];     // per-slice denominator partials (4MB)
__device__ float g_ctxp[NSL*ROWS*E_];     // per-slice ctx partials (32MB)

// ---------------------------------------------------------------------------
// 64-wide GEMM, j-pair packed: Y[r][e] = act(scale*(sum_j X[r][j]W[e][j]+b[e]))
// X and W staged ROW-MAJOR in padded smem (conflict-free), inner loop reads
// (j, j+1) pairs via 8-byte LDS and does packed fma2; horizontal add at end.
// dh_transpose: remap OUTPUT column e -> (e&7)*8+(e>>3)  (attn layout)
// wperm:        remap W's j index (X cols are in d*8+h layout)
// ---------------------------------------------------------------------------
__global__ __launch_bounds__(256) void gemm64(
    const float* __restrict__ X, const float* __restrict__ W,
    const float* __restrict__ bias, float* __restrict__ Y,
    float scale, int relu, int dh_transpose, int wperm)
{
    __shared__ float xs[64][66];
    __shared__ float Ws[64][66];

    const int t = threadIdx.x;
    const int rowbase = blockIdx.x * 64;

#pragma unroll
    for (int kk = 0; kk < 16; kk++) {
        int idx = t + kk * 256;
        int r = idx >> 6, c = idx & 63;          // consecutive t -> consecutive c
        xs[r][c] = X[(size_t)(rowbase + r) * 64 + c];
        int cc = wperm ? ((c & 7) * 8 + (c >> 3)) : c;
        Ws[r][c] = W[r * 64 + cc];               // row-major, conflict-free STS
    }
    __syncthreads();

    const int tx = t & 15;                        // cols tx + c*16
    const int ty = t >> 4;                        // rows ty*4 + rr

    u64t acc2[4][4];
#pragma unroll
    for (int rr = 0; rr < 4; rr++)
#pragma unroll
        for (int c = 0; c < 4; c++) acc2[rr][c] = 0ull;

#pragma unroll 8
    for (int j2 = 0; j2 < 32; j2++) {
        u64t xv[4], wv[4];
#pragma unroll
        for (int rr = 0; rr < 4; rr++)
            xv[rr] = *(const u64t*)&xs[ty * 4 + rr][2 * j2];
#pragma unroll
        for (int c = 0; c < 4; c++)
            wv[c] = *(const u64t*)&Ws[tx + c * 16][2 * j2];
#pragma unroll
        for (int rr = 0; rr < 4; rr++)
#pragma unroll
            for (int c = 0; c < 4; c++)
                acc2[rr][c] = fma2(xv[rr], wv[c], acc2[rr][c]);
    }

#pragma unroll
    for (int c = 0; c < 4; c++) {
        int col = tx + c * 16;
        float bb = bias[col];
        int ocol = dh_transpose ? ((col & 7) * 8 + (col >> 3)) : col;
#pragma unroll
        for (int rr = 0; rr < 4; rr++) {
            float lo, hi; unpack2(acc2[rr][c], lo, hi);
            float v = scale * ((lo + hi) + bb);
            if (relu) v = fmaxf(v, 0.0f);
            Y[(size_t)(rowbase + ty * 4 + rr) * 64 + ocol] = v;
        }
    }
}

// ---------------------------------------------------------------------------
// Attention pass 1: per-slice softmax denominator partials.
// Grid (4 qtiles, NSL slices, B). Block 128 thr = 4 warps x 32 queries.
// Lane owns one query (all 8 heads); K staged in smem 64-key tiles (broadcast
// LDS). q/k in [d*8+h] layout; q pre-scaled by QK_SCALE*log2(e).
// ---------------------------------------------------------------------------
__global__ __launch_bounds__(128, 5) void attn_pass1(
    const float* __restrict__ qh, const float* __restrict__ kh,
    float* __restrict__ part)
{
    __shared__ float Ks[64 * 64];   // 16KB

    const int b    = blockIdx.z;
    const int sl   = blockIdx.y;
    const int tid  = threadIdx.x;
    const int warp = tid >> 5;
    const int lane = tid & 31;
    const size_t qi = (size_t)b * L_ + blockIdx.x * 128 + warp * 32 + lane;

    u64t q2[32];
    {
        const ulonglong2* qp = (const ulonglong2*)(qh + qi * 64);
#pragma unroll
        for (int j = 0; j < 16; j++) {
            ulonglong2 v = qp[j];
            q2[2 * j] = v.x; q2[2 * j + 1] = v.y;
        }
    }

    float sum[8];
#pragma unroll
    for (int h = 0; h < 8; h++) sum[h] = 0.0f;

    for (int c = 0; c < SLK / 64; c++) {
        __syncthreads();
        {
            const float4* src =
                (const float4*)(kh + ((size_t)b * L_ + sl * SLK + c * 64) * 64);
            float4* dst = (float4*)Ks;
#pragma unroll
            for (int j = 0; j < 8; j++)
                dst[tid + j * 128] = src[tid + j * 128];
        }
        __syncthreads();
#pragma unroll 2
        for (int mm = 0; mm < 64; mm++) {
            const ulonglong2* kp = (const ulonglong2*)(Ks + mm * 64);
            u64t acc[4];
            {
                ulonglong2 ka = kp[0], kc = kp[1];
                acc[0] = mul2(q2[0], ka.x);
                acc[1] = mul2(q2[1], ka.y);
                acc[2] = mul2(q2[2], kc.x);
                acc[3] = mul2(q2[3], kc.y);
            }
#pragma unroll
            for (int d = 1; d < 8; d++) {
                ulonglong2 ka = kp[2 * d], kc = kp[2 * d + 1];
                acc[0] = fma2(q2[d * 4 + 0], ka.x, acc[0]);
                acc[1] = fma2(q2[d * 4 + 1], ka.y, acc[1]);
                acc[2] = fma2(q2[d * 4 + 2], kc.x, acc[2]);
                acc[3] = fma2(q2[d * 4 + 3], kc.y, acc[3]);
            }
#pragma unroll
            for (int p = 0; p < 4; p++) {
                float lo, hi; unpack2(acc[p], lo, hi);
                sum[2 * p]     += ex2f(lo);
                sum[2 * p + 1] += ex2f(hi);
            }
        }
    }

    float4* op = (float4*)(part + qi * (NSL * 8) + sl * 8);
    op[0] = make_float4(sum[0], sum[1], sum[2], sum[3]);
    op[1] = make_float4(sum[4], sum[5], sum[6], sum[7]);
}

// ---------------------------------------------------------------------------
// Attention pass 2: per-slice NORMALIZED ctx partials + attn_wts head-mean.
// li_h = -log2(denominator) folded into the QK accumulator init, so ex2
// yields the normalized p directly — no inv multiplies anywhere downstream.
// ---------------------------------------------------------------------------
__global__ __launch_bounds__(128) void attn_pass2(
    const float* __restrict__ qh, const float* __restrict__ kh,
    const float* __restrict__ vh, const float* __restrict__ part,
    float* __restrict__ ctxp, float* __restrict__ attn_out)
{
    __shared__ float Ks[64 * 64];          // 16KB
    __shared__ float Vs[64 * 64];          // 16KB
    __shared__ float Wtile[4][32][17];     // 8.5KB

    const int b    = blockIdx.z;
    const int sl   = blockIdx.y;
    const int tid  = threadIdx.x;
    const int warp = tid >> 5;
    const int lane = tid & 31;
    const size_t qi = (size_t)b * L_ + blockIdx.x * 128 + warp * 32 + lane;

    u64t q2[32];
    {
        const ulonglong2* qp = (const ulonglong2*)(qh + qi * 64);
#pragma unroll
        for (int j = 0; j < 16; j++) {
            ulonglong2 v = qp[j];
            q2[2 * j] = v.x; q2[2 * j + 1] = v.y;
        }
    }

    // li2[p] = (-log2(sum_{2p}), -log2(sum_{2p+1})) from pass-1 partials
    u64t li2[4];
    {
        float s[8];
#pragma unroll
        for (int h = 0; h < 8; h++) s[h] = 0.0f;
        const float4* pp = (const float4*)(part + qi * (NSL * 8));
#pragma unroll
        for (int ss = 0; ss < NSL; ss++) {
            float4 a = pp[2 * ss], c = pp[2 * ss + 1];
            s[0] += a.x; s[1] += a.y; s[2] += a.z; s[3] += a.w;
            s[4] += c.x; s[5] += c.y; s[6] += c.z; s[7] += c.w;
        }
#pragma unroll
        for (int p = 0; p < 4; p++)
            li2[p] = pack2(-lg2f(s[2 * p]), -lg2f(s[2 * p + 1]));
    }

    u64t ctx2[32];
#pragma unroll
    for (int j = 0; j < 32; j++) ctx2[j] = 0ull;

    for (int c = 0; c < SLK / 64; c++) {
        __syncthreads();
        {
            const float4* ksrc =
                (const float4*)(kh + ((size_t)b * L_ + sl * SLK + c * 64) * 64);
            const float4* vsrc =
                (const float4*)(vh + ((size_t)b * L_ + sl * SLK + c * 64) * 64);
            float4* kdst = (float4*)Ks;
            float4* vdst = (float4*)Vs;
#pragma unroll
            for (int j = 0; j < 8; j++) {
                kdst[tid + j * 128] = ksrc[tid + j * 128];
                vdst[tid + j * 128] = vsrc[tid + j * 128];
            }
        }
        __syncthreads();

        for (int m16 = 0; m16 < 64; m16 += 16) {
#pragma unroll 2
            for (int mm = 0; mm < 16; mm++) {
                const int m = m16 + mm;
                const ulonglong2* kp = (const ulonglong2*)(Ks + m * 64);
                u64t acc[4];
                {
                    ulonglong2 ka = kp[0], kc = kp[1];
                    acc[0] = fma2(q2[0], ka.x, li2[0]);
                    acc[1] = fma2(q2[1], ka.y, li2[1]);
                    acc[2] = fma2(q2[2], kc.x, li2[2]);
                    acc[3] = fma2(q2[3], kc.y, li2[3]);
                }
#pragma unroll
                for (int d = 1; d < 8; d++) {
                    ulonglong2 ka = kp[2 * d], kc = kp[2 * d + 1];
                    acc[0] = fma2(q2[d * 4 + 0], ka.x, acc[0]);
                    acc[1] = fma2(q2[d * 4 + 1], ka.y, acc[1]);
                    acc[2] = fma2(q2[d * 4 + 2], kc.x, acc[2]);
                    acc[3] = fma2(q2[d * 4 + 3], kc.y, acc[3]);
                }
                float e[8];
#pragma unroll
                for (int p = 0; p < 4; p++) {
                    float lo, hi; unpack2(acc[p], lo, hi);
                    e[2 * p]     = ex2f(lo);     // normalized p
                    e[2 * p + 1] = ex2f(hi);
                }
                float w = e[0] + e[1];
#pragma unroll
                for (int h = 2; h < 8; h++) w += e[h];
                Wtile[warp][lane][mm] = w * 0.125f;

                u64t e2[4];
#pragma unroll
                for (int p = 0; p < 4; p++) e2[p] = pack2(e[2 * p], e[2 * p + 1]);

                const ulonglong2* vp = (const ulonglong2*)(Vs + m * 64);
#pragma unroll
                for (int d = 0; d < 8; d++) {
                    ulonglong2 va = vp[2 * d], vc = vp[2 * d + 1];
                    ctx2[d * 4 + 0] = fma2(e2[0], va.x, ctx2[d * 4 + 0]);
                    ctx2[d * 4 + 1] = fma2(e2[1], va.y, ctx2[d * 4 + 1]);
                    ctx2[d * 4 + 2] = fma2(e2[2], vc.x, ctx2[d * 4 + 2]);
                    ctx2[d * 4 + 3] = fma2(e2[3], vc.y, ctx2[d * 4 + 3]);
                }
            }
            // flush 32 queries x 16 keys (transposed -> coalesced 64B rows)
            __syncwarp();
            {
                const int m0 = sl * SLK + c * 64 + m16;
                float* arow = attn_out +
                    ((size_t)b * L_ + blockIdx.x * 128 + warp * 32) * L_ + m0;
                const int col = lane & 15;
#pragma unroll
                for (int rr = 0; rr < 16; rr++) {
                    int row = rr * 2 + (lane >> 4);
                    arow[(size_t)row * L_ + col] = Wtile[warp][row][col];
                }
            }
            __syncwarp();
        }
    }

    // store normalized ctx partial for this slice
    ulonglong2* cp = (ulonglong2*)(ctxp + (size_t)sl * ROWS * 64 + qi * 64);
#pragma unroll
    for (int d = 0; d < 8; d++) {
        ulonglong2 a, c;
        a.x = ctx2[d * 4 + 0]; a.y = ctx2[d * 4 + 1];
        c.x = ctx2[d * 4 + 2]; c.y = ctx2[d * 4 + 3];
        cp[2 * d] = a; cp[2 * d + 1] = c;
    }
}

// ---------------------------------------------------------------------------
// Combine ctx partials across slices (pure sum; partials already normalized).
// Output stays in [d*8+h] layout (Wo GEMM uses wperm).
// ---------------------------------------------------------------------------
__global__ __launch_bounds__(256) void ctx_combine(
    const float* __restrict__ ctxp, float* __restrict__ ctx)
{
    const int t  = blockIdx.x * 256 + threadIdx.x;   // 0 .. ROWS*16-1
    const size_t off = (size_t)t * 4;

    float4 s = ((const float4*)(ctxp + off))[0];
#pragma unroll
    for (int ss = 1; ss < NSL; ss++) {
        float4 a = ((const float4*)(ctxp + (size_t)ss * ROWS * 64 + off))[0];
        s.x += a.x; s.y += a.y; s.z += a.z; s.w += a.w;
    }
    ((float4*)(ctx + off))[0] = s;
}

// ---------------------------------------------------------------------------
// Residual add + LayerNorm over E=64. One warp per row; lane covers 2 cols.
// ---------------------------------------------------------------------------
__global__ __launch_bounds__(256) void ln_add_kernel(
    const float* __restrict__ a, const float* __restrict__ bres,
    const float* __restrict__ g, const float* __restrict__ beta,
    float* __restrict__ out)
{
    const int warp = threadIdx.x >> 5;
    const int lane = threadIdx.x & 31;
    const int row  = blockIdx.x * 8 + warp;

    float2 av = ((const float2*)(a    + (size_t)row * 64))[lane];
    float2 bv = ((const float2*)(bres + (size_t)row * 64))[lane];
    float x0 = av.x + bv.x;
    float x1 = av.y + bv.y;

    float s  = x0 + x1;
    float sq = fmaf(x0, x0, x1 * x1);
#pragma unroll
    for (int o = 16; o > 0; o >>= 1) {
        s  += __shfl_xor_sync(0xffffffffu, s,  o);
        sq += __shfl_xor_sync(0xffffffffu, sq, o);
    }
    float mu   = s * (1.0f / 64.0f);
    float var  = sq * (1.0f / 64.0f) - mu * mu;
    float rstd = rsqrtf(var + 1e-5f);

    float2 gv = ((const float2*)g)[lane];
    float2 bb = ((const float2*)beta)[lane];
    float2 o2;
    o2.x = fmaf((x0 - mu) * rstd, gv.x, bb.x);
    o2.y = fmaf((x1 - mu) * rstd, gv.y, bb.y);
    ((float2*)(out + (size_t)row * 64))[lane] = o2;
}

// ---------------------------------------------------------------------------
extern "C" void kernel_launch(void* const* d_in, const int* in_sizes, int n_in,
                              void* d_out, int out_size)
{
    const float* q    = (const float*)d_in[0];
    const float* k    = (const float*)d_in[1];
    const float* prev = (const float*)d_in[2];
    const float* Wq   = (const float*)d_in[3];
    const float* bq   = (const float*)d_in[4];
    const float* Wk   = (const float*)d_in[5];
    const float* bk   = (const float*)d_in[6];
    const float* Wv   = (const float*)d_in[7];
    const float* bv   = (const float*)d_in[8];
    const float* Wo   = (const float*)d_in[9];
    const float* bo   = (const float*)d_in[10];
    const float* g1   = (const float*)d_in[11];
    const float* be1  = (const float*)d_in[12];
    const float* W1   = (const float*)d_in[13];
    const float* b1   = (const float*)d_in[14];
    const float* W2   = (const float*)d_in[15];
    const float* b2   = (const float*)d_in[16];
    const float* g2   = (const float*)d_in[17];
    const float* be2  = (const float*)d_in[18];

    float* outp = (float*)d_out;                    // [B, Lq, E]
    float* attn = outp + (size_t)ROWS * E_;         // [B, Lq, Lk]

    float *qh, *khp, *vhp, *ctx, *t0, *xbuf, *f1, *p1, *ctxp;
    cudaGetSymbolAddress((void**)&qh,  g_qh);
    cudaGetSymbolAddress((void**)&khp, g_kh);
    cudaGetSymbolAddress((void**)&vhp, g_vh);
    cudaGetSymbolAddress((void**)&ctx, g_ctx);
    cudaGetSymbolAddress((void**)&t0,  g_t0);
    cudaGetSymbolAddress((void**)&xbuf,g_x);
    cudaGetSymbolAddress((void**)&f1,  g_f1);
    cudaGetSymbolAddress((void**)&p1,  g_p1);
    cudaGetSymbolAddress((void**)&ctxp,g_ctxp);

    const int GB = ROWS / 64;   // 512 blocks per gemm
    // projections into [d*8+h] layout; q pre-scaled by QK_SCALE*log2(e)
    gemm64<<<GB, 256>>>(q, Wq, bq, qh,  QK_SCALE * LOG2E_F, 0, 1, 0);
    gemm64<<<GB, 256>>>(k, Wk, bk, khp, 1.0f, 0, 1, 0);
    gemm64<<<GB, 256>>>(k, Wv, bv, vhp, 1.0f, 0, 1, 0);

    attn_pass1<<<dim3(L_ / 128, NSL, B_), 128>>>(qh, khp, p1);
    attn_pass2<<<dim3(L_ / 128, NSL, B_), 128>>>(qh, khp, vhp, p1, ctxp, attn);
    ctx_combine<<<ROWS * 16 / 256, 256>>>(ctxp, ctx);

    gemm64<<<GB, 256>>>(ctx, Wo, bo, t0, 1.0f, 0, 0, 1);
    ln_add_kernel<<<ROWS / 8, 256>>>(t0, prev, g1, be1, xbuf);

    gemm64<<<GB, 256>>>(xbuf, W1, b1, f1, 1.0f, 1, 0, 0);
    gemm64<<<GB, 256>>>(f1, W2, b2, t0, 1.0f, 0, 0, 0);
    ln_add_kernel<<<ROWS / 8, 256>>>(t0, xbuf, g2, be2, outp);
}

// round 7
// speedup vs baseline: 1.1478x; 1.1478x over previous
#include <cuda_runtime.h>
#include <cuda_fp16.h>
#include <math.h>

#define B_ 64
#define L_ 512
#define E_ 64
#define H_ 8
#define D_ 8
#define ROWS (B_*L_)          // 32768
#define QK_SCALE 0.35355339059327373f   // 1/sqrt(8)
#define LOG2E_F  1.4426950408889634f
#define NSL 4                 // key slices
#define SLK (L_/NSL)          // 128 keys per slice

typedef unsigned long long u64t;

// ---- packed f32x2 helpers (ptxas never auto-fuses; PTX only) ----
__device__ __forceinline__ u64t fma2(u64t a, u64t b, u64t c) {
    u64t d; asm("fma.rn.f32x2 %0, %1, %2, %3;" : "=l"(d) : "l"(a), "l"(b), "l"(c)); return d;
}
__device__ __forceinline__ u64t mul2(u64t a, u64t b) {
    u64t d; asm("mul.rn.f32x2 %0, %1, %2;" : "=l"(d) : "l"(a), "l"(b)); return d;
}
__device__ __forceinline__ u64t pack2(float lo, float hi) {
    u64t d; asm("mov.b64 %0, {%1, %2};" : "=l"(d) : "f"(lo), "f"(hi)); return d;
}
__device__ __forceinline__ void unpack2(u64t a, float& lo, float& hi) {
    asm("mov.b64 {%0, %1}, %2;" : "=f"(lo), "=f"(hi) : "l"(a));
}
__device__ __forceinline__ float ex2f(float x) {
    float r; asm("ex2.approx.f32 %0, %1;" : "=f"(r) : "f"(x)); return r;
}
__device__ __forceinline__ float lg2f(float x) {
    float r; asm("lg2.approx.f32 %0, %1;" : "=f"(r) : "f"(x)); return r;
}

// ---- scratch (static device arrays; no allocation) ----
__device__ float  g_qh  [ROWS*E_];
__device__ float  g_kh  [ROWS*E_];
__device__ float  g_vh  [ROWS*E_];
__device__ float  g_ctx [ROWS*E_];
__device__ float  g_t0  [ROWS*E_];
__device__ float  g_x   [ROWS*E_];
__device__ float  g_f1  [ROWS*E_];
__device__ float  g_p1  [ROWS*NSL*H_];     // per-slice denominator partials
__device__ float  g_ctxp[NSL*ROWS*E_];     // per-slice ctx partials (32MB)
__device__ __half g_wp  [(size_t)ROWS*L_]; // fp16 head-half attn partial (33MB)

// ---------------------------------------------------------------------------
// 64-wide GEMM, 32 rows / 128 threads / 1024 blocks (single-wave residency).
// Y[r][e] = act( scale * ( sum_j X[r][j]*W[e][j] + bias[e] ) )
// X and W staged row-major in padded smem; j-pair packed fma2 inner loop.
// dh_transpose: remap OUTPUT column e -> (e&7)*8+(e>>3)  (attn layout)
// wperm:        remap W's j index (X cols are in d*8+h layout)
// ---------------------------------------------------------------------------
__global__ __launch_bounds__(128) void gemm64(
    const float* __restrict__ X, const float* __restrict__ W,
    const float* __restrict__ bias, float* __restrict__ Y,
    float scale, int relu, int dh_transpose, int wperm)
{
    __shared__ float xs[32][66];
    __shared__ float Ws[64][66];

    const int t = threadIdx.x;
    const int rowbase = blockIdx.x * 32;

#pragma unroll
    for (int kk = 0; kk < 16; kk++) {            // X: 32x64
        int idx = t + kk * 128;
        int r = idx >> 6, c = idx & 63;
        xs[r][c] = X[(size_t)(rowbase + r) * 64 + c];
    }
#pragma unroll
    for (int kk = 0; kk < 32; kk++) {            // W: 64x64
        int idx = t + kk * 128;
        int r = idx >> 6, c = idx & 63;
        int cc = wperm ? ((c & 7) * 8 + (c >> 3)) : c;
        Ws[r][c] = W[r * 64 + cc];
    }
    __syncthreads();

    const int tx = t & 15;                        // cols tx + c*16
    const int ty = t >> 4;                        // rows ty*4 + rr

    u64t acc2[4][4];
#pragma unroll
    for (int rr = 0; rr < 4; rr++)
#pragma unroll
        for (int c = 0; c < 4; c++) acc2[rr][c] = 0ull;

#pragma unroll 8
    for (int j2 = 0; j2 < 32; j2++) {
        u64t xv[4], wv[4];
#pragma unroll
        for (int rr = 0; rr < 4; rr++)
            xv[rr] = *(const u64t*)&xs[ty * 4 + rr][2 * j2];
#pragma unroll
        for (int c = 0; c < 4; c++)
            wv[c] = *(const u64t*)&Ws[tx + c * 16][2 * j2];
#pragma unroll
        for (int rr = 0; rr < 4; rr++)
#pragma unroll
            for (int c = 0; c < 4; c++)
                acc2[rr][c] = fma2(xv[rr], wv[c], acc2[rr][c]);
    }

#pragma unroll
    for (int c = 0; c < 4; c++) {
        int col = tx + c * 16;
        float bb = bias[col];
        int ocol = dh_transpose ? ((col & 7) * 8 + (col >> 3)) : col;
#pragma unroll
        for (int rr = 0; rr < 4; rr++) {
            float lo, hi; unpack2(acc2[rr][c], lo, hi);
            float v = scale * ((lo + hi) + bb);
            if (relu) v = fmaxf(v, 0.0f);
            Y[(size_t)(rowbase + ty * 4 + rr) * 64 + ocol] = v;
        }
    }
}

// ---------------------------------------------------------------------------
// Attention pass 1: per-slice softmax denominator partials.   (R5-proven)
// Grid (4 qtiles, NSL, B). Block 128 thr = 4 warps x 32 queries.
// Lane owns one query (all 8 heads); K staged in smem 64-key tiles.
// q/k in [d*8+h] layout; q pre-scaled by QK_SCALE*log2(e).
// ---------------------------------------------------------------------------
__global__ __launch_bounds__(128) void attn_pass1(
    const float* __restrict__ qh, const float* __restrict__ kh,
    float* __restrict__ part)
{
    __shared__ float Ks[64 * 64];   // 16KB

    const int b    = blockIdx.z;
    const int sl   = blockIdx.y;
    const int tid  = threadIdx.x;
    const int warp = tid >> 5;
    const int lane = tid & 31;
    const size_t qi = (size_t)b * L_ + blockIdx.x * 128 + warp * 32 + lane;

    u64t q2[32];
    {
        const ulonglong2* qp = (const ulonglong2*)(qh + qi * 64);
#pragma unroll
        for (int j = 0; j < 16; j++) {
            ulonglong2 v = qp[j];
            q2[2 * j] = v.x; q2[2 * j + 1] = v.y;
        }
    }

    float sum[8];
#pragma unroll
    for (int h = 0; h < 8; h++) sum[h] = 0.0f;

    for (int c = 0; c < SLK / 64; c++) {
        __syncthreads();
        {
            const float4* src =
                (const float4*)(kh + ((size_t)b * L_ + sl * SLK + c * 64) * 64);
            float4* dst = (float4*)Ks;
#pragma unroll
            for (int j = 0; j < 8; j++)
                dst[tid + j * 128] = src[tid + j * 128];
        }
        __syncthreads();
#pragma unroll 2
        for (int mm = 0; mm < 64; mm++) {
            const ulonglong2* kp = (const ulonglong2*)(Ks + mm * 64);
            u64t acc[4];
            {
                ulonglong2 ka = kp[0], kc = kp[1];
                acc[0] = mul2(q2[0], ka.x);
                acc[1] = mul2(q2[1], ka.y);
                acc[2] = mul2(q2[2], kc.x);
                acc[3] = mul2(q2[3], kc.y);
            }
#pragma unroll
            for (int d = 1; d < 8; d++) {
                ulonglong2 ka = kp[2 * d], kc = kp[2 * d + 1];
                acc[0] = fma2(q2[d * 4 + 0], ka.x, acc[0]);
                acc[1] = fma2(q2[d * 4 + 1], ka.y, acc[1]);
                acc[2] = fma2(q2[d * 4 + 2], kc.x, acc[2]);
                acc[3] = fma2(q2[d * 4 + 3], kc.y, acc[3]);
            }
#pragma unroll
            for (int p = 0; p < 4; p++) {
                float lo, hi; unpack2(acc[p], lo, hi);
                sum[2 * p]     += ex2f(lo);
                sum[2 * p + 1] += ex2f(hi);
            }
        }
    }

    float4* op = (float4*)(part + qi * (NSL * 8) + sl * 8);
    op[0] = make_float4(sum[0], sum[1], sum[2], sum[3]);
    op[1] = make_float4(sum[4], sum[5], sum[6], sum[7]);
}

// ---------------------------------------------------------------------------
// Attention pass 2, head-half HH (heads HH*4 .. HH*4+3).
// Lane owns one query, 4 heads -> half the register state of full pass 2.
// li = -log2(denom) folded into QK accumulator init => ex2 gives normalized p.
// HH=0: store 4-head partial attn mean as fp16 into wp.
// HH=1: add wp partial, write final fp32 attn_out.
// ctx partials: each half writes its disjoint 32 floats of [d*8+h] rows.
// ---------------------------------------------------------------------------
template <int HH>
__global__ __launch_bounds__(128, 5) void attn_pass2_half(
    const float* __restrict__ qh, const float* __restrict__ kh,
    const float* __restrict__ vh, const float* __restrict__ part,
    float* __restrict__ ctxp, __half* __restrict__ wp,
    float* __restrict__ attn_out)
{
    __shared__ float Ks[64 * 32];          // 8KB  (half rows)
    __shared__ float Vs[64 * 32];          // 8KB
    __shared__ float Wtile[4][32][17];     // 8.5KB

    const int b    = blockIdx.z;
    const int sl   = blockIdx.y;
    const int tid  = threadIdx.x;
    const int warp = tid >> 5;
    const int lane = tid & 31;
    const size_t qi = (size_t)b * L_ + blockIdx.x * 128 + warp * 32 + lane;

    // q half: dims d, heads HH*4..HH*4+3  -> 16 u64
    u64t q2[16];
    {
        const float* qp = qh + qi * 64 + HH * 4;
#pragma unroll
        for (int d = 0; d < 8; d++) {
            ulonglong2 v = *(const ulonglong2*)(qp + d * 8);
            q2[2 * d] = v.x; q2[2 * d + 1] = v.y;
        }
    }

    // li2[p] = -log2(denominator) for this half's head pairs
    u64t li2[2];
    {
        float s[4] = {0.0f, 0.0f, 0.0f, 0.0f};
        const float4* pp = (const float4*)(part + qi * (NSL * 8));
#pragma unroll
        for (int ss = 0; ss < NSL; ss++) {
            float4 a = pp[2 * ss + HH];
            s[0] += a.x; s[1] += a.y; s[2] += a.z; s[3] += a.w;
        }
        li2[0] = pack2(-lg2f(s[0]), -lg2f(s[1]));
        li2[1] = pack2(-lg2f(s[2]), -lg2f(s[3]));
    }

    u64t ctx2[16];
#pragma unroll
    for (int j = 0; j < 16; j++) ctx2[j] = 0ull;

    for (int c = 0; c < SLK / 64; c++) {
        __syncthreads();
        {
            // stage half-rows: 64 keys x 8 dims x 16B  (512 float4 per tile)
            const size_t rowb = ((size_t)b * L_ + sl * SLK + c * 64);
            const float4* ksrc = (const float4*)kh;
            const float4* vsrc = (const float4*)vh;
            float4* kdst = (float4*)Ks;
            float4* vdst = (float4*)Vs;
#pragma unroll
            for (int it = 0; it < 4; it++) {
                int cidx = tid + it * 128;      // 0..511
                int m = cidx >> 3, d = cidx & 7;
                size_t sidx = (rowb + m) * 16 + d * 2 + HH;
                kdst[m * 8 + d] = ksrc[sidx];
                vdst[m * 8 + d] = vsrc[sidx];
            }
        }
        __syncthreads();

        for (int m16 = 0; m16 < 64; m16 += 16) {
#pragma unroll 2
            for (int mm = 0; mm < 16; mm++) {
                const int m = m16 + mm;
                const ulonglong2* kp = (const ulonglong2*)(Ks + m * 32);
                u64t acc0 = li2[0], acc1 = li2[1];
#pragma unroll
                for (int d = 0; d < 8; d++) {
                    ulonglong2 kd = kp[d];
                    acc0 = fma2(q2[2 * d],     kd.x, acc0);
                    acc1 = fma2(q2[2 * d + 1], kd.y, acc1);
                }
                float e0, e1, e2v, e3v;
                { float lo, hi; unpack2(acc0, lo, hi); e0 = ex2f(lo); e1 = ex2f(hi); }
                { float lo, hi; unpack2(acc1, lo, hi); e2v = ex2f(lo); e3v = ex2f(hi); }
                Wtile[warp][lane][mm] = (e0 + e1 + e2v + e3v) * 0.125f;

                u64t ep0 = pack2(e0, e1), ep1 = pack2(e2v, e3v);
                const ulonglong2* vp = (const ulonglong2*)(Vs + m * 32);
#pragma unroll
                for (int d = 0; d < 8; d++) {
                    ulonglong2 vd = vp[d];
                    ctx2[2 * d]     = fma2(ep0, vd.x, ctx2[2 * d]);
                    ctx2[2 * d + 1] = fma2(ep1, vd.y, ctx2[2 * d + 1]);
                }
            }
            // flush 32 queries x 16 keys (transposed -> coalesced)
            __syncwarp();
            {
                const int m0 = sl * SLK + c * 64 + m16;
                const size_t row0 = (size_t)b * L_ + blockIdx.x * 128 + warp * 32;
                const int col = lane & 15;
#pragma unroll
                for (int rr = 0; rr < 16; rr++) {
                    int row = rr * 2 + (lane >> 4);
                    float wv = Wtile[warp][row][col];
                    if (HH == 0) {
                        wp[(row0 + row) * L_ + m0 + col] = __float2half(wv);
                    } else {
                        attn_out[(row0 + row) * L_ + m0 + col] =
                            wv + __half2float(wp[(row0 + row) * L_ + m0 + col]);
                    }
                }
            }
            __syncwarp();
        }
    }

    // store this half's normalized ctx partial (disjoint 16B chunks)
    float* cb = ctxp + (size_t)sl * ROWS * 64 + qi * 64 + HH * 4;
#pragma unroll
    for (int d = 0; d < 8; d++) {
        ulonglong2 v;
        v.x = ctx2[2 * d]; v.y = ctx2[2 * d + 1];
        *(ulonglong2*)(cb + d * 8) = v;
    }
}

// ---------------------------------------------------------------------------
// Combine ctx partials across slices (pure sum; already normalized).
// ---------------------------------------------------------------------------
__global__ __launch_bounds__(256) void ctx_combine(
    const float* __restrict__ ctxp, float* __restrict__ ctx)
{
    const int t  = blockIdx.x * 256 + threadIdx.x;   // 0 .. ROWS*16-1
    const size_t off = (size_t)t * 4;

    float4 s = ((const float4*)(ctxp + off))[0];
#pragma unroll
    for (int ss = 1; ss < NSL; ss++) {
        float4 a = ((const float4*)(ctxp + (size_t)ss * ROWS * 64 + off))[0];
        s.x += a.x; s.y += a.y; s.z += a.z; s.w += a.w;
    }
    ((float4*)(ctx + off))[0] = s;
}

// ---------------------------------------------------------------------------
// Residual add + LayerNorm over E=64. One warp per row; lane covers 2 cols.
// ---------------------------------------------------------------------------
__global__ __launch_bounds__(256) void ln_add_kernel(
    const float* __restrict__ a, const float* __restrict__ bres,
    const float* __restrict__ g, const float* __restrict__ beta,
    float* __restrict__ out)
{
    const int warp = threadIdx.x >> 5;
    const int lane = threadIdx.x & 31;
    const int row  = blockIdx.x * 8 + warp;

    float2 av = ((const float2*)(a    + (size_t)row * 64))[lane];
    float2 bv = ((const float2*)(bres + (size_t)row * 64))[lane];
    float x0 = av.x + bv.x;
    float x1 = av.y + bv.y;

    float s  = x0 + x1;
    float sq = fmaf(x0, x0, x1 * x1);
#pragma unroll
    for (int o = 16; o > 0; o >>= 1) {
        s  += __shfl_xor_sync(0xffffffffu, s,  o);
        sq += __shfl_xor_sync(0xffffffffu, sq, o);
    }
    float mu   = s * (1.0f / 64.0f);
    float var  = sq * (1.0f / 64.0f) - mu * mu;
    float rstd = rsqrtf(var + 1e-5f);

    float2 gv = ((const float2*)g)[lane];
    float2 bb = ((const float2*)beta)[lane];
    float2 o2;
    o2.x = fmaf((x0 - mu) * rstd, gv.x, bb.x);
    o2.y = fmaf((x1 - mu) * rstd, gv.y, bb.y);
    ((float2*)(out + (size_t)row * 64))[lane] = o2;
}

// ---------------------------------------------------------------------------
extern "C" void kernel_launch(void* const* d_in, const int* in_sizes, int n_in,
                              void* d_out, int out_size)
{
    const float* q    = (const float*)d_in[0];
    const float* k    = (const float*)d_in[1];
    const float* prev = (const float*)d_in[2];
    const float* Wq   = (const float*)d_in[3];
    const float* bq   = (const float*)d_in[4];
    const float* Wk   = (const float*)d_in[5];
    const float* bk   = (const float*)d_in[6];
    const float* Wv   = (const float*)d_in[7];
    const float* bv   = (const float*)d_in[8];
    const float* Wo   = (const float*)d_in[9];
    const float* bo   = (const float*)d_in[10];
    const float* g1   = (const float*)d_in[11];
    const float* be1  = (const float*)d_in[12];
    const float* W1   = (const float*)d_in[13];
    const float* b1   = (const float*)d_in[14];
    const float* W2   = (const float*)d_in[15];
    const float* b2   = (const float*)d_in[16];
    const float* g2   = (const float*)d_in[17];
    const float* be2  = (const float*)d_in[18];

    float* outp = (float*)d_out;                    // [B, Lq, E]
    float* attn = outp + (size_t)ROWS * E_;         // [B, Lq, Lk]

    float *qh, *khp, *vhp, *ctx, *t0, *xbuf, *f1, *p1, *ctxp;
    __half* wp;
    cudaGetSymbolAddress((void**)&qh,  g_qh);
    cudaGetSymbolAddress((void**)&khp, g_kh);
    cudaGetSymbolAddress((void**)&vhp, g_vh);
    cudaGetSymbolAddress((void**)&ctx, g_ctx);
    cudaGetSymbolAddress((void**)&t0,  g_t0);
    cudaGetSymbolAddress((void**)&xbuf,g_x);
    cudaGetSymbolAddress((void**)&f1,  g_f1);
    cudaGetSymbolAddress((void**)&p1,  g_p1);
    cudaGetSymbolAddress((void**)&ctxp,g_ctxp);
    cudaGetSymbolAddress((void**)&wp,  g_wp);

    const int GB = ROWS / 32;   // 1024 blocks per gemm (single wave)
    // projections into [d*8+h] layout; q pre-scaled by QK_SCALE*log2(e)
    gemm64<<<GB, 128>>>(q, Wq, bq, qh,  QK_SCALE * LOG2E_F, 0, 1, 0);
    gemm64<<<GB, 128>>>(k, Wk, bk, khp, 1.0f, 0, 1, 0);
    gemm64<<<GB, 128>>>(k, Wv, bv, vhp, 1.0f, 0, 1, 0);

    attn_pass1<<<dim3(L_ / 128, NSL, B_), 128>>>(qh, khp, p1);
    attn_pass2_half<0><<<dim3(L_ / 128, NSL, B_), 128>>>(qh, khp, vhp, p1,
                                                         ctxp, wp, attn);
    attn_pass2_half<1><<<dim3(L_ / 128, NSL, B_), 128>>>(qh, khp, vhp, p1,
                                                         ctxp, wp, attn);
    ctx_combine<<<ROWS * 16 / 256, 256>>>(ctxp, ctx);

    gemm64<<<GB, 128>>>(ctx, Wo, bo, t0, 1.0f, 0, 0, 1);
    ln_add_kernel<<<ROWS / 8, 256>>>(t0, prev, g1, be1, xbuf);

    gemm64<<<GB, 128>>>(xbuf, W1, b1, f1, 1.0f, 1, 0, 0);
    gemm64<<<GB, 128>>>(f1, W2, b2, t0, 1.0f, 0, 0, 0);
    ln_add_kernel<<<ROWS / 8, 256>>>(t0, xbuf, g2, be2, outp);
}

// round 8
// speedup vs baseline: 1.3138x; 1.1446x over previous
#include <cuda_runtime.h>
#include <math.h>

#define B_ 64
#define L_ 512
#define E_ 64
#define H_ 8
#define D_ 8
#define ROWS (B_*L_)          // 32768
#define QK_SCALE 0.35355339059327373f   // 1/sqrt(8)
#define LOG2E_F  1.4426950408889634f
#define NSL 4                 // key slices
#define SLK (L_/NSL)          // 128 keys per slice

typedef unsigned long long u64t;

// ---- packed f32x2 helpers (ptxas never auto-fuses; PTX only) ----
__device__ __forceinline__ u64t fma2(u64t a, u64t b, u64t c) {
    u64t d; asm("fma.rn.f32x2 %0, %1, %2, %3;" : "=l"(d) : "l"(a), "l"(b), "l"(c)); return d;
}
__device__ __forceinline__ u64t mul2(u64t a, u64t b) {
    u64t d; asm("mul.rn.f32x2 %0, %1, %2;" : "=l"(d) : "l"(a), "l"(b)); return d;
}
__device__ __forceinline__ u64t pack2(float lo, float hi) {
    u64t d; asm("mov.b64 %0, {%1, %2};" : "=l"(d) : "f"(lo), "f"(hi)); return d;
}
__device__ __forceinline__ void unpack2(u64t a, float& lo, float& hi) {
    asm("mov.b64 {%0, %1}, %2;" : "=f"(lo), "=f"(hi) : "l"(a));
}
__device__ __forceinline__ float ex2f(float x) {
    float r; asm("ex2.approx.f32 %0, %1;" : "=f"(r) : "f"(x)); return r;
}
__device__ __forceinline__ float lg2f(float x) {
    float r; asm("lg2.approx.f32 %0, %1;" : "=f"(r) : "f"(x)); return r;
}

// ---- scratch (static device arrays; no allocation) ----
__device__ float g_qh  [ROWS*E_];
__device__ float g_kh  [ROWS*E_];
__device__ float g_vh  [ROWS*E_];
__device__ float g_ctx [ROWS*E_];
__device__ float g_t0  [ROWS*E_];
__device__ float g_x   [ROWS*E_];
__device__ float g_f1  [ROWS*E_];
__device__ float g_p1  [ROWS*NSL*H_];     // per-slice denominator partials
__device__ float g_ctxp[NSL*ROWS*E_];     // per-slice ctx partials (32MB)

// ---------------------------------------------------------------------------
// 64-wide GEMM, 32 rows / 128 threads / 1024 blocks (single-wave residency).
// Y[r][e] = act( scale * ( sum_j X[r][j]*W[e][j] + bias[e] ) )
// dh_transpose: remap OUTPUT column e -> (e&7)*8+(e>>3)  (attn layout)
// wperm:        remap W's j index (X cols are in d*8+h layout)
// ---------------------------------------------------------------------------
__global__ __launch_bounds__(128) void gemm64(
    const float* __restrict__ X, const float* __restrict__ W,
    const float* __restrict__ bias, float* __restrict__ Y,
    float scale, int relu, int dh_transpose, int wperm)
{
    __shared__ float xs[32][66];
    __shared__ float Ws[64][66];

    const int t = threadIdx.x;
    const int rowbase = blockIdx.x * 32;

#pragma unroll
    for (int kk = 0; kk < 16; kk++) {            // X: 32x64
        int idx = t + kk * 128;
        int r = idx >> 6, c = idx & 63;
        xs[r][c] = X[(size_t)(rowbase + r) * 64 + c];
    }
#pragma unroll
    for (int kk = 0; kk < 32; kk++) {            // W: 64x64
        int idx = t + kk * 128;
        int r = idx >> 6, c = idx & 63;
        int cc = wperm ? ((c & 7) * 8 + (c >> 3)) : c;
        Ws[r][c] = W[r * 64 + cc];
    }
    __syncthreads();

    const int tx = t & 15;
    const int ty = t >> 4;

    u64t acc2[4][4];
#pragma unroll
    for (int rr = 0; rr < 4; rr++)
#pragma unroll
        for (int c = 0; c < 4; c++) acc2[rr][c] = 0ull;

#pragma unroll 8
    for (int j2 = 0; j2 < 32; j2++) {
        u64t xv[4], wv[4];
#pragma unroll
        for (int rr = 0; rr < 4; rr++)
            xv[rr] = *(const u64t*)&xs[ty * 4 + rr][2 * j2];
#pragma unroll
        for (int c = 0; c < 4; c++)
            wv[c] = *(const u64t*)&Ws[tx + c * 16][2 * j2];
#pragma unroll
        for (int rr = 0; rr < 4; rr++)
#pragma unroll
            for (int c = 0; c < 4; c++)
                acc2[rr][c] = fma2(xv[rr], wv[c], acc2[rr][c]);
    }

#pragma unroll
    for (int c = 0; c < 4; c++) {
        int col = tx + c * 16;
        float bb = bias[col];
        int ocol = dh_transpose ? ((col & 7) * 8 + (col >> 3)) : col;
#pragma unroll
        for (int rr = 0; rr < 4; rr++) {
            float lo, hi; unpack2(acc2[rr][c], lo, hi);
            float v = scale * ((lo + hi) + bb);
            if (relu) v = fmaxf(v, 0.0f);
            Y[(size_t)(rowbase + ty * 4 + rr) * 64 + ocol] = v;
        }
    }
}

// ---------------------------------------------------------------------------
// Attention pass 1: per-slice softmax denominator partials, head-half warps.
// Block 256 thr = 8 warps: warp = qg*2 + hh. Lane owns one query (qg group
// of 32), 4 heads (hh half). K staged in shared 32-key tiles used by all
// warps. q/k in [d*8+h] layout; q pre-scaled by QK_SCALE*log2(e).
// Grid (L/128, NSL, B).
// ---------------------------------------------------------------------------
__global__ __launch_bounds__(256) void attn_pass1(
    const float* __restrict__ qh, const float* __restrict__ kh,
    float* __restrict__ part)
{
    __shared__ float Ks[32 * 64];   // 8KB

    const int b    = blockIdx.z;
    const int sl   = blockIdx.y;
    const int tid  = threadIdx.x;
    const int warp = tid >> 5;
    const int lane = tid & 31;
    const int qg   = warp >> 1;
    const int hh   = warp & 1;
    const size_t qi = (size_t)b * L_ + blockIdx.x * 128 + qg * 32 + lane;

    // q half: 8 dims x 4 heads -> 16 u64
    u64t q2[16];
    {
        const float* qp = qh + qi * 64 + hh * 4;
#pragma unroll
        for (int d = 0; d < 8; d++) {
            ulonglong2 v = *(const ulonglong2*)(qp + d * 8);
            q2[2 * d] = v.x; q2[2 * d + 1] = v.y;
        }
    }

    float sum[4] = {0.0f, 0.0f, 0.0f, 0.0f};

    for (int t = 0; t < SLK / 32; t++) {
        __syncthreads();
        {
            const float4* src =
                (const float4*)(kh + ((size_t)b * L_ + sl * SLK + t * 32) * 64);
            float4* dst = (float4*)Ks;
            dst[tid]       = src[tid];
            dst[tid + 256] = src[tid + 256];
        }
        __syncthreads();
#pragma unroll 4
        for (int m = 0; m < 32; m++) {
            const float* krow = Ks + m * 64 + hh * 4;
            u64t acc0, acc1;
            {
                ulonglong2 kd = *(const ulonglong2*)krow;
                acc0 = mul2(q2[0], kd.x);
                acc1 = mul2(q2[1], kd.y);
            }
#pragma unroll
            for (int d = 1; d < 8; d++) {
                ulonglong2 kd = *(const ulonglong2*)(krow + d * 8);
                acc0 = fma2(q2[2 * d],     kd.x, acc0);
                acc1 = fma2(q2[2 * d + 1], kd.y, acc1);
            }
            float lo, hi;
            unpack2(acc0, lo, hi); sum[0] += ex2f(lo); sum[1] += ex2f(hi);
            unpack2(acc1, lo, hi); sum[2] += ex2f(lo); sum[3] += ex2f(hi);
        }
    }

    ((float4*)(part + qi * (NSL * 8) + sl * 8 + hh * 4))[0] =
        make_float4(sum[0], sum[1], sum[2], sum[3]);
}

// ---------------------------------------------------------------------------
// Attention pass 2: per-slice NORMALIZED ctx partials + fp32 attn_wts.
// Same (qg, hh) warp mapping. li = -log2(denom) folded into QK accumulator
// init => ex2 yields normalized p. Both head-halves live in one block:
// their 4-head sums meet in Wtile and are combined to fp32 attn_out every
// 16 keys (syncthreads pair). ctx halves write disjoint 16B chunks.
// ---------------------------------------------------------------------------
__global__ __launch_bounds__(256) void attn_pass2(
    const float* __restrict__ qh, const float* __restrict__ kh,
    const float* __restrict__ vh, const float* __restrict__ part,
    float* __restrict__ ctxp, float* __restrict__ attn_out)
{
    __shared__ float Ks[32 * 64];          // 8KB
    __shared__ float Vs[32 * 64];          // 8KB
    __shared__ float Wtile[8][32][17];     // 17KB

    const int b    = blockIdx.z;
    const int sl   = blockIdx.y;
    const int tid  = threadIdx.x;
    const int warp = tid >> 5;
    const int lane = tid & 31;
    const int qg   = warp >> 1;
    const int hh   = warp & 1;
    const size_t qi = (size_t)b * L_ + blockIdx.x * 128 + qg * 32 + lane;

    u64t q2[16];
    {
        const float* qp = qh + qi * 64 + hh * 4;
#pragma unroll
        for (int d = 0; d < 8; d++) {
            ulonglong2 v = *(const ulonglong2*)(qp + d * 8);
            q2[2 * d] = v.x; q2[2 * d + 1] = v.y;
        }
    }

    // li2 = -log2(total denominator) for this half's 4 heads
    u64t li2[2];
    {
        float s[4] = {0.0f, 0.0f, 0.0f, 0.0f};
        const float4* pp = (const float4*)(part + qi * (NSL * 8));
#pragma unroll
        for (int ss = 0; ss < NSL; ss++) {
            float4 a = pp[2 * ss + hh];
            s[0] += a.x; s[1] += a.y; s[2] += a.z; s[3] += a.w;
        }
        li2[0] = pack2(-lg2f(s[0]), -lg2f(s[1]));
        li2[1] = pack2(-lg2f(s[2]), -lg2f(s[3]));
    }

    u64t ctx2[16];
#pragma unroll
    for (int j = 0; j < 16; j++) ctx2[j] = 0ull;

    for (int t = 0; t < SLK / 32; t++) {
        __syncthreads();
        {
            const size_t rowb = ((size_t)b * L_ + sl * SLK + t * 32) * 16;
            const float4* ksrc = (const float4*)kh + rowb;
            const float4* vsrc = (const float4*)vh + rowb;
            float4* kdst = (float4*)Ks;
            float4* vdst = (float4*)Vs;
            kdst[tid]       = ksrc[tid];
            kdst[tid + 256] = ksrc[tid + 256];
            vdst[tid]       = vsrc[tid];
            vdst[tid + 256] = vsrc[tid + 256];
        }
        __syncthreads();

        for (int half = 0; half < 2; half++) {
#pragma unroll 2
            for (int mm = 0; mm < 16; mm++) {
                const int m = half * 16 + mm;
                const float* krow = Ks + m * 64 + hh * 4;
                u64t acc0 = li2[0], acc1 = li2[1];
#pragma unroll
                for (int d = 0; d < 8; d++) {
                    ulonglong2 kd = *(const ulonglong2*)(krow + d * 8);
                    acc0 = fma2(q2[2 * d],     kd.x, acc0);
                    acc1 = fma2(q2[2 * d + 1], kd.y, acc1);
                }
                float e0, e1, e2v, e3v;
                { float lo, hi; unpack2(acc0, lo, hi); e0 = ex2f(lo); e1 = ex2f(hi); }
                { float lo, hi; unpack2(acc1, lo, hi); e2v = ex2f(lo); e3v = ex2f(hi); }
                Wtile[warp][lane][mm] = (e0 + e1) + (e2v + e3v);

                u64t ep0 = pack2(e0, e1), ep1 = pack2(e2v, e3v);
                const float* vrow = Vs + m * 64 + hh * 4;
#pragma unroll
                for (int d = 0; d < 8; d++) {
                    ulonglong2 vd = *(const ulonglong2*)(vrow + d * 8);
                    ctx2[2 * d]     = fma2(ep0, vd.x, ctx2[2 * d]);
                    ctx2[2 * d + 1] = fma2(ep1, vd.y, ctx2[2 * d + 1]);
                }
            }
            // combine hh halves -> fp32 attn_out (whole block cooperates)
            __syncthreads();
            {
                const int m0 = sl * SLK + t * 32 + half * 16;
                const size_t row0 = (size_t)b * L_ + blockIdx.x * 128;
#pragma unroll
                for (int it = 0; it < 8; it++) {
                    int idx = tid + it * 256;           // 0..2047
                    int c   = idx & 15;
                    int r   = (idx >> 4) & 31;
                    int qg2 = idx >> 9;
                    float w = (Wtile[qg2 * 2][r][c] + Wtile[qg2 * 2 + 1][r][c])
                              * 0.125f;
                    attn_out[(row0 + qg2 * 32 + r) * L_ + m0 + c] = w;
                }
            }
            __syncthreads();
        }
    }

    // store this half's normalized ctx partial (disjoint 16B chunks)
    float* cb = ctxp + (size_t)sl * ROWS * 64 + qi * 64 + hh * 4;
#pragma unroll
    for (int d = 0; d < 8; d++) {
        ulonglong2 v;
        v.x = ctx2[2 * d]; v.y = ctx2[2 * d + 1];
        *(ulonglong2*)(cb + d * 8) = v;
    }
}

// ---------------------------------------------------------------------------
// Combine ctx partials across slices (pure sum; already normalized).
// ---------------------------------------------------------------------------
__global__ __launch_bounds__(256) void ctx_combine(
    const float* __restrict__ ctxp, float* __restrict__ ctx)
{
    const int t  = blockIdx.x * 256 + threadIdx.x;   // 0 .. ROWS*16-1
    const size_t off = (size_t)t * 4;

    float4 s = ((const float4*)(ctxp + off))[0];
#pragma unroll
    for (int ss = 1; ss < NSL; ss++) {
        float4 a = ((const float4*)(ctxp + (size_t)ss * ROWS * 64 + off))[0];
        s.x += a.x; s.y += a.y; s.z += a.z; s.w += a.w;
    }
    ((float4*)(ctx + off))[0] = s;
}

// ---------------------------------------------------------------------------
// Residual add + LayerNorm over E=64. One warp per row; lane covers 2 cols.
// ---------------------------------------------------------------------------
__global__ __launch_bounds__(256) void ln_add_kernel(
    const float* __restrict__ a, const float* __restrict__ bres,
    const float* __restrict__ g, const float* __restrict__ beta,
    float* __restrict__ out)
{
    const int warp = threadIdx.x >> 5;
    const int lane = threadIdx.x & 31;
    const int row  = blockIdx.x * 8 + warp;

    float2 av = ((const float2*)(a    + (size_t)row * 64))[lane];
    float2 bv = ((const float2*)(bres + (size_t)row * 64))[lane];
    float x0 = av.x + bv.x;
    float x1 = av.y + bv.y;

    float s  = x0 + x1;
    float sq = fmaf(x0, x0, x1 * x1);
#pragma unroll
    for (int o = 16; o > 0; o >>= 1) {
        s  += __shfl_xor_sync(0xffffffffu, s,  o);
        sq += __shfl_xor_sync(0xffffffffu, sq, o);
    }
    float mu   = s * (1.0f / 64.0f);
    float var  = sq * (1.0f / 64.0f) - mu * mu;
    float rstd = rsqrtf(var + 1e-5f);

    float2 gv = ((const float2*)g)[lane];
    float2 bb = ((const float2*)beta)[lane];
    float2 o2;
    o2.x = fmaf((x0 - mu) * rstd, gv.x, bb.x);
    o2.y = fmaf((x1 - mu) * rstd, gv.y, bb.y);
    ((float2*)(out + (size_t)row * 64))[lane] = o2;
}

// ---------------------------------------------------------------------------
extern "C" void kernel_launch(void* const* d_in, const int* in_sizes, int n_in,
                              void* d_out, int out_size)
{
    const float* q    = (const float*)d_in[0];
    const float* k    = (const float*)d_in[1];
    const float* prev = (const float*)d_in[2];
    const float* Wq   = (const float*)d_in[3];
    const float* bq   = (const float*)d_in[4];
    const float* Wk   = (const float*)d_in[5];
    const float* bk   = (const float*)d_in[6];
    const float* Wv   = (const float*)d_in[7];
    const float* bv   = (const float*)d_in[8];
    const float* Wo   = (const float*)d_in[9];
    const float* bo   = (const float*)d_in[10];
    const float* g1   = (const float*)d_in[11];
    const float* be1  = (const float*)d_in[12];
    const float* W1   = (const float*)d_in[13];
    const float* b1   = (const float*)d_in[14];
    const float* W2   = (const float*)d_in[15];
    const float* b2   = (const float*)d_in[16];
    const float* g2   = (const float*)d_in[17];
    const float* be2  = (const float*)d_in[18];

    float* outp = (float*)d_out;                    // [B, Lq, E]
    float* attn = outp + (size_t)ROWS * E_;         // [B, Lq, Lk]

    float *qh, *khp, *vhp, *ctx, *t0, *xbuf, *f1, *p1, *ctxp;
    cudaGetSymbolAddress((void**)&qh,  g_qh);
    cudaGetSymbolAddress((void**)&khp, g_kh);
    cudaGetSymbolAddress((void**)&vhp, g_vh);
    cudaGetSymbolAddress((void**)&ctx, g_ctx);
    cudaGetSymbolAddress((void**)&t0,  g_t0);
    cudaGetSymbolAddress((void**)&xbuf,g_x);
    cudaGetSymbolAddress((void**)&f1,  g_f1);
    cudaGetSymbolAddress((void**)&p1,  g_p1);
    cudaGetSymbolAddress((void**)&ctxp,g_ctxp);

    const int GB = ROWS / 32;   // 1024 blocks per gemm (single wave)
    // projections into [d*8+h] layout; q pre-scaled by QK_SCALE*log2(e)
    gemm64<<<GB, 128>>>(q, Wq, bq, qh,  QK_SCALE * LOG2E_F, 0, 1, 0);
    gemm64<<<GB, 128>>>(k, Wk, bk, khp, 1.0f, 0, 1, 0);
    gemm64<<<GB, 128>>>(k, Wv, bv, vhp, 1.0f, 0, 1, 0);

    attn_pass1<<<dim3(L_ / 128, NSL, B_), 256>>>(qh, khp, p1);
    attn_pass2<<<dim3(L_ / 128, NSL, B_), 256>>>(qh, khp, vhp, p1, ctxp, attn);
    ctx_combine<<<ROWS * 16 / 256, 256>>>(ctxp, ctx);

    gemm64<<<GB, 128>>>(ctx, Wo, bo, t0, 1.0f, 0, 0, 1);
    ln_add_kernel<<<ROWS / 8, 256>>>(t0, prev, g1, be1, xbuf);

    gemm64<<<GB, 128>>>(xbuf, W1, b1, f1, 1.0f, 1, 0, 0);
    gemm64<<<GB, 128>>>(f1, W2, b2, t0, 1.0f, 0, 0, 0);
    ln_add_kernel<<<ROWS / 8, 256>>>(t0, xbuf, g2, be2, outp);
}

// round 9
// speedup vs baseline: 1.3362x; 1.0171x over previous
#include <cuda_runtime.h>
#include <math.h>

#define B_ 64
#define L_ 512
#define E_ 64
#define H_ 8
#define D_ 8
#define ROWS (B_*L_)          // 32768
#define QK_SCALE 0.35355339059327373f   // 1/sqrt(8)
#define LOG2E_F  1.4426950408889634f
#define NSL 4                 // key slices
#define SLK (L_/NSL)          // 128 keys per slice

typedef unsigned long long u64t;

// ---- packed f32x2 helpers (ptxas never auto-fuses; PTX only) ----
__device__ __forceinline__ u64t fma2(u64t a, u64t b, u64t c) {
    u64t d; asm("fma.rn.f32x2 %0, %1, %2, %3;" : "=l"(d) : "l"(a), "l"(b), "l"(c)); return d;
}
__device__ __forceinline__ u64t mul2(u64t a, u64t b) {
    u64t d; asm("mul.rn.f32x2 %0, %1, %2;" : "=l"(d) : "l"(a), "l"(b)); return d;
}
__device__ __forceinline__ u64t pack2(float lo, float hi) {
    u64t d; asm("mov.b64 %0, {%1, %2};" : "=l"(d) : "f"(lo), "f"(hi)); return d;
}
__device__ __forceinline__ void unpack2(u64t a, float& lo, float& hi) {
    asm("mov.b64 {%0, %1}, %2;" : "=f"(lo), "=f"(hi) : "l"(a));
}
__device__ __forceinline__ float ex2f(float x) {
    float r; asm("ex2.approx.f32 %0, %1;" : "=f"(r) : "f"(x)); return r;
}
__device__ __forceinline__ float lg2f(float x) {
    float r; asm("lg2.approx.f32 %0, %1;" : "=f"(r) : "f"(x)); return r;
}
__device__ __forceinline__ void barpair(int id) {
    asm volatile("bar.sync %0, 64;" :: "r"(id) : "memory");
}

// ---- scratch (static device arrays; no allocation) ----
__device__ float g_qh  [ROWS*E_];
__device__ float g_kh  [ROWS*E_];
__device__ float g_vh  [ROWS*E_];
__device__ float g_ctx [ROWS*E_];
__device__ float g_t0  [ROWS*E_];
__device__ float g_x   [ROWS*E_];
__device__ float g_f1  [ROWS*E_];
__device__ float g_p1  [ROWS*NSL*H_];     // per-slice denominator partials
__device__ float g_ctxp[NSL*ROWS*E_];     // per-slice ctx partials (32MB)

// ---------------------------------------------------------------------------
// 64-wide GEMM, 32 rows / 128 threads / 1024 blocks (single-wave residency).
// Y[r][e] = act( scale * ( sum_j X[r][j]*W[e][j] + bias[e] ) )
// dh_transpose: remap OUTPUT column e -> (e&7)*8+(e>>3)  (attn layout)
// wperm:        remap W's j index (X cols are in d*8+h layout)
// ---------------------------------------------------------------------------
__global__ __launch_bounds__(128) void gemm64(
    const float* __restrict__ X, const float* __restrict__ W,
    const float* __restrict__ bias, float* __restrict__ Y,
    float scale, int relu, int dh_transpose, int wperm)
{
    __shared__ float xs[32][66];
    __shared__ float Ws[64][66];

    const int t = threadIdx.x;
    const int rowbase = blockIdx.x * 32;

#pragma unroll
    for (int kk = 0; kk < 16; kk++) {            // X: 32x64
        int idx = t + kk * 128;
        int r = idx >> 6, c = idx & 63;
        xs[r][c] = X[(size_t)(rowbase + r) * 64 + c];
    }
#pragma unroll
    for (int kk = 0; kk < 32; kk++) {            // W: 64x64
        int idx = t + kk * 128;
        int r = idx >> 6, c = idx & 63;
        int cc = wperm ? ((c & 7) * 8 + (c >> 3)) : c;
        Ws[r][c] = W[r * 64 + cc];
    }
    __syncthreads();

    const int tx = t & 15;
    const int ty = t >> 4;

    u64t acc2[4][4];
#pragma unroll
    for (int rr = 0; rr < 4; rr++)
#pragma unroll
        for (int c = 0; c < 4; c++) acc2[rr][c] = 0ull;

#pragma unroll 8
    for (int j2 = 0; j2 < 32; j2++) {
        u64t xv[4], wv[4];
#pragma unroll
        for (int rr = 0; rr < 4; rr++)
            xv[rr] = *(const u64t*)&xs[ty * 4 + rr][2 * j2];
#pragma unroll
        for (int c = 0; c < 4; c++)
            wv[c] = *(const u64t*)&Ws[tx + c * 16][2 * j2];
#pragma unroll
        for (int rr = 0; rr < 4; rr++)
#pragma unroll
            for (int c = 0; c < 4; c++)
                acc2[rr][c] = fma2(xv[rr], wv[c], acc2[rr][c]);
    }

#pragma unroll
    for (int c = 0; c < 4; c++) {
        int col = tx + c * 16;
        float bb = bias[col];
        int ocol = dh_transpose ? ((col & 7) * 8 + (col >> 3)) : col;
#pragma unroll
        for (int rr = 0; rr < 4; rr++) {
            float lo, hi; unpack2(acc2[rr][c], lo, hi);
            float v = scale * ((lo + hi) + bb);
            if (relu) v = fmaxf(v, 0.0f);
            Y[(size_t)(rowbase + ty * 4 + rr) * 64 + ocol] = v;
        }
    }
}

// ---------------------------------------------------------------------------
// Attention pass 1: per-slice softmax denominator partials, head-half warps.
// Block 256 thr = 8 warps: warp = qg*2 + hh. Lane owns one query (qg group
// of 32), 4 heads (hh half). WHOLE 128-key slice staged in smem once (32KB),
// so only one barrier pair per kernel. q/k in [d*8+h] layout; q pre-scaled
// by QK_SCALE*log2(e). Grid (L/128, NSL, B).
// ---------------------------------------------------------------------------
__global__ __launch_bounds__(256) void attn_pass1(
    const float* __restrict__ qh, const float* __restrict__ kh,
    float* __restrict__ part)
{
    __shared__ float Ks[SLK * 64];   // 32KB

    const int b    = blockIdx.z;
    const int sl   = blockIdx.y;
    const int tid  = threadIdx.x;
    const int warp = tid >> 5;
    const int lane = tid & 31;
    const int qg   = warp >> 1;
    const int hh   = warp & 1;
    const size_t qi = (size_t)b * L_ + blockIdx.x * 128 + qg * 32 + lane;

    // q half: 8 dims x 4 heads -> 16 u64
    u64t q2[16];
    {
        const float* qp = qh + qi * 64 + hh * 4;
#pragma unroll
        for (int d = 0; d < 8; d++) {
            ulonglong2 v = *(const ulonglong2*)(qp + d * 8);
            q2[2 * d] = v.x; q2[2 * d + 1] = v.y;
        }
    }

    // stage full slice (2048 float4, 8 per thread)
    {
        const float4* src =
            (const float4*)(kh + ((size_t)b * L_ + sl * SLK) * 64);
        float4* dst = (float4*)Ks;
#pragma unroll
        for (int j = 0; j < 8; j++)
            dst[tid + j * 256] = src[tid + j * 256];
    }
    __syncthreads();

    float sum[4] = {0.0f, 0.0f, 0.0f, 0.0f};

#pragma unroll 4
    for (int m = 0; m < SLK; m++) {
        const float* krow = Ks + m * 64 + hh * 4;
        u64t acc0, acc1;
        {
            ulonglong2 kd = *(const ulonglong2*)krow;
            acc0 = mul2(q2[0], kd.x);
            acc1 = mul2(q2[1], kd.y);
        }
#pragma unroll
        for (int d = 1; d < 8; d++) {
            ulonglong2 kd = *(const ulonglong2*)(krow + d * 8);
            acc0 = fma2(q2[2 * d],     kd.x, acc0);
            acc1 = fma2(q2[2 * d + 1], kd.y, acc1);
        }
        float lo, hi;
        unpack2(acc0, lo, hi); sum[0] += ex2f(lo); sum[1] += ex2f(hi);
        unpack2(acc1, lo, hi); sum[2] += ex2f(lo); sum[3] += ex2f(hi);
    }

    ((float4*)(part + qi * (NSL * 8) + sl * 8 + hh * 4))[0] =
        make_float4(sum[0], sum[1], sum[2], sum[3]);
}

// ---------------------------------------------------------------------------
// Attention pass 2: per-slice NORMALIZED ctx partials + fp32 attn_wts.
// Same (qg, hh) warp mapping. li = -log2(denom) folded into QK accumulator
// init => ex2 yields normalized p. 64-key K+V tiles (2 per slice). Head-half
// combine for attn_wts done per warp-PAIR with 64-thread named barriers
// (no full-block sync inside the key loop).
// ---------------------------------------------------------------------------
__global__ __launch_bounds__(256) void attn_pass2(
    const float* __restrict__ qh, const float* __restrict__ kh,
    const float* __restrict__ vh, const float* __restrict__ part,
    float* __restrict__ ctxp, float* __restrict__ attn_out)
{
    __shared__ float Ks[64 * 64];          // 16KB
    __shared__ float Vs[64 * 64];          // 16KB
    __shared__ float Wtile[8][32][17];     // 17.4KB

    const int b    = blockIdx.z;
    const int sl   = blockIdx.y;
    const int tid  = threadIdx.x;
    const int warp = tid >> 5;
    const int lane = tid & 31;
    const int qg   = warp >> 1;
    const int hh   = warp & 1;
    const int lt   = tid & 63;             // id within warp-pair
    const size_t qi = (size_t)b * L_ + blockIdx.x * 128 + qg * 32 + lane;

    u64t q2[16];
    {
        const float* qp = qh + qi * 64 + hh * 4;
#pragma unroll
        for (int d = 0; d < 8; d++) {
            ulonglong2 v = *(const ulonglong2*)(qp + d * 8);
            q2[2 * d] = v.x; q2[2 * d + 1] = v.y;
        }
    }

    // li2 = -log2(total denominator) for this half's 4 heads
    u64t li2[2];
    {
        float s[4] = {0.0f, 0.0f, 0.0f, 0.0f};
        const float4* pp = (const float4*)(part + qi * (NSL * 8));
#pragma unroll
        for (int ss = 0; ss < NSL; ss++) {
            float4 a = pp[2 * ss + hh];
            s[0] += a.x; s[1] += a.y; s[2] += a.z; s[3] += a.w;
        }
        li2[0] = pack2(-lg2f(s[0]), -lg2f(s[1]));
        li2[1] = pack2(-lg2f(s[2]), -lg2f(s[3]));
    }

    u64t ctx2[16];
#pragma unroll
    for (int j = 0; j < 16; j++) ctx2[j] = 0ull;

    for (int t = 0; t < SLK / 64; t++) {
        __syncthreads();
        {
            const size_t rowb = ((size_t)b * L_ + sl * SLK + t * 64) * 16;
            const float4* ksrc = (const float4*)kh + rowb;
            const float4* vsrc = (const float4*)vh + rowb;
            float4* kdst = (float4*)Ks;
            float4* vdst = (float4*)Vs;
#pragma unroll
            for (int j = 0; j < 4; j++) {
                kdst[tid + j * 256] = ksrc[tid + j * 256];
                vdst[tid + j * 256] = vsrc[tid + j * 256];
            }
        }
        __syncthreads();

        for (int chunk = 0; chunk < 4; chunk++) {
#pragma unroll 2
            for (int mm = 0; mm < 16; mm++) {
                const int m = chunk * 16 + mm;
                const float* krow = Ks + m * 64 + hh * 4;
                u64t acc0 = li2[0], acc1 = li2[1];
#pragma unroll
                for (int d = 0; d < 8; d++) {
                    ulonglong2 kd = *(const ulonglong2*)(krow + d * 8);
                    acc0 = fma2(q2[2 * d],     kd.x, acc0);
                    acc1 = fma2(q2[2 * d + 1], kd.y, acc1);
                }
                float e0, e1, e2v, e3v;
                { float lo, hi; unpack2(acc0, lo, hi); e0 = ex2f(lo); e1 = ex2f(hi); }
                { float lo, hi; unpack2(acc1, lo, hi); e2v = ex2f(lo); e3v = ex2f(hi); }
                Wtile[warp][lane][mm] = (e0 + e1) + (e2v + e3v);

                u64t ep0 = pack2(e0, e1), ep1 = pack2(e2v, e3v);
                const float* vrow = Vs + m * 64 + hh * 4;
#pragma unroll
                for (int d = 0; d < 8; d++) {
                    ulonglong2 vd = *(const ulonglong2*)(vrow + d * 8);
                    ctx2[2 * d]     = fma2(ep0, vd.x, ctx2[2 * d]);
                    ctx2[2 * d + 1] = fma2(ep1, vd.y, ctx2[2 * d + 1]);
                }
            }
            // pair-combine hh halves -> fp32 attn_out (64-thread barrier)
            barpair(1 + qg);
            {
                const int m0 = sl * SLK + t * 64 + chunk * 16;
                const size_t row0 = (size_t)b * L_ + blockIdx.x * 128 + qg * 32;
#pragma unroll
                for (int it = 0; it < 8; it++) {
                    int idx = lt + it * 64;             // 0..511
                    int c   = idx & 15;
                    int r   = idx >> 4;                 // 0..31
                    float w = (Wtile[qg * 2][r][c] + Wtile[qg * 2 + 1][r][c])
                              * 0.125f;
                    attn_out[(row0 + r) * L_ + m0 + c] = w;
                }
            }
            barpair(1 + qg);
        }
    }

    // store this half's normalized ctx partial (disjoint 16B chunks)
    float* cb = ctxp + (size_t)sl * ROWS * 64 + qi * 64 + hh * 4;
#pragma unroll
    for (int d = 0; d < 8; d++) {
        ulonglong2 v;
        v.x = ctx2[2 * d]; v.y = ctx2[2 * d + 1];
        *(ulonglong2*)(cb + d * 8) = v;
    }
}

// ---------------------------------------------------------------------------
// Combine ctx partials across slices (pure sum; already normalized).
// ---------------------------------------------------------------------------
__global__ __launch_bounds__(256) void ctx_combine(
    const float* __restrict__ ctxp, float* __restrict__ ctx)
{
    const int t  = blockIdx.x * 256 + threadIdx.x;   // 0 .. ROWS*16-1
    const size_t off = (size_t)t * 4;

    float4 s = ((const float4*)(ctxp + off))[0];
#pragma unroll
    for (int ss = 1; ss < NSL; ss++) {
        float4 a = ((const float4*)(ctxp + (size_t)ss * ROWS * 64 + off))[0];
        s.x += a.x; s.y += a.y; s.z += a.z; s.w += a.w;
    }
    ((float4*)(ctx + off))[0] = s;
}

// ---------------------------------------------------------------------------
// Residual add + LayerNorm over E=64. One warp per row; lane covers 2 cols.
// ---------------------------------------------------------------------------
__global__ __launch_bounds__(256) void ln_add_kernel(
    const float* __restrict__ a, const float* __restrict__ bres,
    const float* __restrict__ g, const float* __restrict__ beta,
    float* __restrict__ out)
{
    const int warp = threadIdx.x >> 5;
    const int lane = threadIdx.x & 31;
    const int row  = blockIdx.x * 8 + warp;

    float2 av = ((const float2*)(a    + (size_t)row * 64))[lane];
    float2 bv = ((const float2*)(bres + (size_t)row * 64))[lane];
    float x0 = av.x + bv.x;
    float x1 = av.y + bv.y;

    float s  = x0 + x1;
    float sq = fmaf(x0, x0, x1 * x1);
#pragma unroll
    for (int o = 16; o > 0; o >>= 1) {
        s  += __shfl_xor_sync(0xffffffffu, s,  o);
        sq += __shfl_xor_sync(0xffffffffu, sq, o);
    }
    float mu   = s * (1.0f / 64.0f);
    float var  = sq * (1.0f / 64.0f) - mu * mu;
    float rstd = rsqrtf(var + 1e-5f);

    float2 gv = ((const float2*)g)[lane];
    float2 bb = ((const float2*)beta)[lane];
    float2 o2;
    o2.x = fmaf((x0 - mu) * rstd, gv.x, bb.x);
    o2.y = fmaf((x1 - mu) * rstd, gv.y, bb.y);
    ((float2*)(out + (size_t)row * 64))[lane] = o2;
}

// ---------------------------------------------------------------------------
extern "C" void kernel_launch(void* const* d_in, const int* in_sizes, int n_in,
                              void* d_out, int out_size)
{
    const float* q    = (const float*)d_in[0];
    const float* k    = (const float*)d_in[1];
    const float* prev = (const float*)d_in[2];
    const float* Wq   = (const float*)d_in[3];
    const float* bq   = (const float*)d_in[4];
    const float* Wk   = (const float*)d_in[5];
    const float* bk   = (const float*)d_in[6];
    const float* Wv   = (const float*)d_in[7];
    const float* bv   = (const float*)d_in[8];
    const float* Wo   = (const float*)d_in[9];
    const float* bo   = (const float*)d_in[10];
    const float* g1   = (const float*)d_in[11];
    const float* be1  = (const float*)d_in[12];
    const float* W1   = (const float*)d_in[13];
    const float* b1   = (const float*)d_in[14];
    const float* W2   = (const float*)d_in[15];
    const float* b2   = (const float*)d_in[16];
    const float* g2   = (const float*)d_in[17];
    const float* be2  = (const float*)d_in[18];

    float* outp = (float*)d_out;                    // [B, Lq, E]
    float* attn = outp + (size_t)ROWS * E_;         // [B, Lq, Lk]

    float *qh, *khp, *vhp, *ctx, *t0, *xbuf, *f1, *p1, *ctxp;
    cudaGetSymbolAddress((void**)&qh,  g_qh);
    cudaGetSymbolAddress((void**)&khp, g_kh);
    cudaGetSymbolAddress((void**)&vhp, g_vh);
    cudaGetSymbolAddress((void**)&ctx, g_ctx);
    cudaGetSymbolAddress((void**)&t0,  g_t0);
    cudaGetSymbolAddress((void**)&xbuf,g_x);
    cudaGetSymbolAddress((void**)&f1,  g_f1);
    cudaGetSymbolAddress((void**)&p1,  g_p1);
    cudaGetSymbolAddress((void**)&ctxp,g_ctxp);

    const int GB = ROWS / 32;   // 1024 blocks per gemm (single wave)
    // projections into [d*8+h] layout; q pre-scaled by QK_SCALE*log2(e)
    gemm64<<<GB, 128>>>(q, Wq, bq, qh,  QK_SCALE * LOG2E_F, 0, 1, 0);
    gemm64<<<GB, 128>>>(k, Wk, bk, khp, 1.0f, 0, 1, 0);
    gemm64<<<GB, 128>>>(k, Wv, bv, vhp, 1.0f, 0, 1, 0);

    attn_pass1<<<dim3(L_ / 128, NSL, B_), 256>>>(qh, khp, p1);
    attn_pass2<<<dim3(L_ / 128, NSL, B_), 256>>>(qh, khp, vhp, p1, ctxp, attn);
    ctx_combine<<<ROWS * 16 / 256, 256>>>(ctxp, ctx);

    gemm64<<<GB, 128>>>(ctx, Wo, bo, t0, 1.0f, 0, 0, 1);
    ln_add_kernel<<<ROWS / 8, 256>>>(t0, prev, g1, be1, xbuf);

    gemm64<<<GB, 128>>>(xbuf, W1, b1, f1, 1.0f, 1, 0, 0);
    gemm64<<<GB, 128>>>(f1, W2, b2, t0, 1.0f, 0, 0, 0);
    ln_add_kernel<<<ROWS / 8, 256>>>(t0, xbuf, g2, be2, outp);
}

// round 10
// speedup vs baseline: 1.4072x; 1.0532x over previous
#include <cuda_runtime.h>
#include <math.h>

#define B_ 64
#define L_ 512
#define E_ 64
#define H_ 8
#define D_ 8
#define ROWS (B_*L_)          // 32768
#define QK_SCALE 0.35355339059327373f   // 1/sqrt(8)
#define LOG2E_F  1.4426950408889634f
#define NSL 4                 // key slices
#define SLK (L_/NSL)          // 128 keys per slice

typedef unsigned long long u64t;

// ---- packed f32x2 helpers (ptxas never auto-fuses; PTX only) ----
__device__ __forceinline__ u64t fma2(u64t a, u64t b, u64t c) {
    u64t d; asm("fma.rn.f32x2 %0, %1, %2, %3;" : "=l"(d) : "l"(a), "l"(b), "l"(c)); return d;
}
__device__ __forceinline__ u64t mul2(u64t a, u64t b) {
    u64t d; asm("mul.rn.f32x2 %0, %1, %2;" : "=l"(d) : "l"(a), "l"(b)); return d;
}
__device__ __forceinline__ u64t pack2(float lo, float hi) {
    u64t d; asm("mov.b64 %0, {%1, %2};" : "=l"(d) : "f"(lo), "f"(hi)); return d;
}
__device__ __forceinline__ void unpack2(u64t a, float& lo, float& hi) {
    asm("mov.b64 {%0, %1}, %2;" : "=f"(lo), "=f"(hi) : "l"(a));
}
__device__ __forceinline__ float ex2f(float x) {
    float r; asm("ex2.approx.f32 %0, %1;" : "=f"(r) : "f"(x)); return r;
}
__device__ __forceinline__ float lg2f(float x) {
    float r; asm("lg2.approx.f32 %0, %1;" : "=f"(r) : "f"(x)); return r;
}
__device__ __forceinline__ void barpair(int id) {
    asm volatile("bar.sync %0, 64;" :: "r"(id) : "memory");
}

// ---- scratch (static device arrays; no allocation) ----
__device__ float g_qh  [ROWS*E_];
__device__ float g_kh  [ROWS*E_];
__device__ float g_vh  [ROWS*E_];
__device__ float g_x   [ROWS*E_];
__device__ float g_f1  [ROWS*E_];
__device__ float g_p1  [ROWS*NSL*H_];     // per-slice denominator partials
__device__ float g_ctxp[NSL*ROWS*E_];     // per-slice ctx partials (32MB)

// ---------------------------------------------------------------------------
// 64-wide GEMM, 32 rows / 128 threads / 1024 blocks (single-wave residency).
// Y[r][e] = act( scale * ( sum_j X[r][j]*W[e][j] + bias[e] ) )
// dh_transpose: remap OUTPUT column e -> (e&7)*8+(e>>3)  (attn layout)
// ---------------------------------------------------------------------------
__global__ __launch_bounds__(128) void gemm64(
    const float* __restrict__ X, const float* __restrict__ W,
    const float* __restrict__ bias, float* __restrict__ Y,
    float scale, int relu, int dh_transpose)
{
    __shared__ float xs[32][66];
    __shared__ float Ws[64][66];

    const int t = threadIdx.x;
    const int rowbase = blockIdx.x * 32;

#pragma unroll
    for (int kk = 0; kk < 16; kk++) {            // X: 32x64
        int idx = t + kk * 128;
        int r = idx >> 6, c = idx & 63;
        xs[r][c] = X[(size_t)(rowbase + r) * 64 + c];
    }
#pragma unroll
    for (int kk = 0; kk < 32; kk++) {            // W: 64x64
        int idx = t + kk * 128;
        int r = idx >> 6, c = idx & 63;
        Ws[r][c] = W[idx];
    }
    __syncthreads();

    const int tx = t & 15;
    const int ty = t >> 4;

    u64t acc2[4][4];
#pragma unroll
    for (int rr = 0; rr < 4; rr++)
#pragma unroll
        for (int c = 0; c < 4; c++) acc2[rr][c] = 0ull;

#pragma unroll 8
    for (int j2 = 0; j2 < 32; j2++) {
        u64t xv[4], wv[4];
#pragma unroll
        for (int rr = 0; rr < 4; rr++)
            xv[rr] = *(const u64t*)&xs[ty * 4 + rr][2 * j2];
#pragma unroll
        for (int c = 0; c < 4; c++)
            wv[c] = *(const u64t*)&Ws[tx + c * 16][2 * j2];
#pragma unroll
        for (int rr = 0; rr < 4; rr++)
#pragma unroll
            for (int c = 0; c < 4; c++)
                acc2[rr][c] = fma2(xv[rr], wv[c], acc2[rr][c]);
    }

#pragma unroll
    for (int c = 0; c < 4; c++) {
        int col = tx + c * 16;
        float bb = bias[col];
        int ocol = dh_transpose ? ((col & 7) * 8 + (col >> 3)) : col;
#pragma unroll
        for (int rr = 0; rr < 4; rr++) {
            float lo, hi; unpack2(acc2[rr][c], lo, hi);
            float v = scale * ((lo + hi) + bb);
            if (relu) v = fmaxf(v, 0.0f);
            Y[(size_t)(rowbase + ty * 4 + rr) * 64 + ocol] = v;
        }
    }
}

// ---------------------------------------------------------------------------
// Fused GEMM + residual add + LayerNorm (for Wo/ln1 and W2/ln2).
// out[r] = LN( X@W^T + bias + resid[r] )
// nsl_sum: X points at ctxp; stage xs as the sum of the NSL slice partials
//          (fuses ctx_combine). wperm: permute W's j index ([d*8+h] inputs).
// ---------------------------------------------------------------------------
__global__ __launch_bounds__(128) void gemm_ln(
    const float* __restrict__ X, const float* __restrict__ W,
    const float* __restrict__ bias, const float* __restrict__ resid,
    const float* __restrict__ g, const float* __restrict__ beta,
    float* __restrict__ out, int wperm, int nsl_sum)
{
    __shared__ float xs[32][66];
    __shared__ float Ws[64][66];
    __shared__ float red[32][8];

    const int t = threadIdx.x;
    const int rowbase = blockIdx.x * 32;

    if (nsl_sum) {
        // xs[r][c] = sum over NSL slices of ctxp  (float4 granularity)
#pragma unroll
        for (int j = 0; j < 4; j++) {
            int fidx = t + j * 128;                  // 0..511 float4s
            size_t gf = (size_t)rowbase * 16 + fidx;
            float4 s = ((const float4*)X)[gf];
#pragma unroll
            for (int ss = 1; ss < NSL; ss++) {
                float4 a = ((const float4*)X)[(size_t)ss * ROWS * 16 + gf];
                s.x += a.x; s.y += a.y; s.z += a.z; s.w += a.w;
            }
            int r = fidx >> 4, c = (fidx & 15) * 4;
            float2* p = (float2*)&xs[r][c];
            p[0] = make_float2(s.x, s.y);
            p[1] = make_float2(s.z, s.w);
        }
    } else {
#pragma unroll
        for (int kk = 0; kk < 16; kk++) {
            int idx = t + kk * 128;
            int r = idx >> 6, c = idx & 63;
            xs[r][c] = X[(size_t)(rowbase + r) * 64 + c];
        }
    }
#pragma unroll
    for (int kk = 0; kk < 32; kk++) {                // W: 64x64
        int idx = t + kk * 128;
        int r = idx >> 6, c = idx & 63;
        int cc = wperm ? ((c & 7) * 8 + (c >> 3)) : c;
        Ws[r][c] = W[r * 64 + cc];
    }
    __syncthreads();

    const int tx = t & 15;
    const int ty = t >> 4;

    u64t acc2[4][4];
#pragma unroll
    for (int rr = 0; rr < 4; rr++)
#pragma unroll
        for (int c = 0; c < 4; c++) acc2[rr][c] = 0ull;

#pragma unroll 8
    for (int j2 = 0; j2 < 32; j2++) {
        u64t xv[4], wv[4];
#pragma unroll
        for (int rr = 0; rr < 4; rr++)
            xv[rr] = *(const u64t*)&xs[ty * 4 + rr][2 * j2];
#pragma unroll
        for (int c = 0; c < 4; c++)
            wv[c] = *(const u64t*)&Ws[tx + c * 16][2 * j2];
#pragma unroll
        for (int rr = 0; rr < 4; rr++)
#pragma unroll
            for (int c = 0; c < 4; c++)
                acc2[rr][c] = fma2(xv[rr], wv[c], acc2[rr][c]);
    }

    __syncthreads();   // done reading xs; reuse it for the pre-LN values
#pragma unroll
    for (int c = 0; c < 4; c++) {
        int col = tx + c * 16;
        float bb = bias[col];
#pragma unroll
        for (int rr = 0; rr < 4; rr++) {
            float lo, hi; unpack2(acc2[rr][c], lo, hi);
            int row = ty * 4 + rr;
            xs[row][col] = (lo + hi) + bb +
                           resid[(size_t)(rowbase + row) * 64 + col];
        }
    }
    __syncthreads();

    // LN over each row of 64: 4 threads per row, 16 cols each
    const int row  = t >> 2;
    const int part = t & 3;
    float lsum = 0.0f, lsq = 0.0f;
#pragma unroll
    for (int j = 0; j < 16; j++) {
        float v = xs[row][part * 16 + j];
        lsum += v;
        lsq  = fmaf(v, v, lsq);
    }
    red[row][part]     = lsum;
    red[row][part + 4] = lsq;
    __syncthreads();

    float s  = red[row][0] + red[row][1] + red[row][2] + red[row][3];
    float sq = red[row][4] + red[row][5] + red[row][6] + red[row][7];
    float mu   = s * (1.0f / 64.0f);
    float var  = sq * (1.0f / 64.0f) - mu * mu;
    float rstd = rsqrtf(var + 1e-5f);

    float4 o[4];
#pragma unroll
    for (int j = 0; j < 16; j++) {
        int c = part * 16 + j;
        ((float*)o)[j] = fmaf((xs[row][c] - mu) * rstd, g[c], beta[c]);
    }
    float4* op = (float4*)(out + (size_t)(rowbase + row) * 64 + part * 16);
#pragma unroll
    for (int j = 0; j < 4; j++) op[j] = o[j];
}

// ---------------------------------------------------------------------------
// Attention pass 1: per-slice softmax denominator partials.
// Block 128 thr = 4 warps: warp = qg*2 + hh. LANE OWNS TWO QUERIES
// (qbase+lane, qbase+32+lane), 4 heads (hh half) => K-row LDS amortized
// over 2x the FMA work. Whole 128-key slice staged once (32KB).
// q/k in [d*8+h] layout; q pre-scaled by QK_SCALE*log2(e).
// Grid (L/128, NSL, B).
// ---------------------------------------------------------------------------
__global__ __launch_bounds__(128) void attn_pass1(
    const float* __restrict__ qh, const float* __restrict__ kh,
    float* __restrict__ part)
{
    __shared__ float Ks[SLK * 64];   // 32KB

    const int b    = blockIdx.z;
    const int sl   = blockIdx.y;
    const int tid  = threadIdx.x;
    const int warp = tid >> 5;
    const int lane = tid & 31;
    const int qg   = warp >> 1;
    const int hh   = warp & 1;
    const size_t qi0 = (size_t)b * L_ + blockIdx.x * 128 + qg * 64 + lane;
    const size_t qi1 = qi0 + 32;

    // two queries' half-head registers: 16 u64 each
    u64t qa[16], qb[16];
    {
        const float* qp0 = qh + qi0 * 64 + hh * 4;
        const float* qp1 = qh + qi1 * 64 + hh * 4;
#pragma unroll
        for (int d = 0; d < 8; d++) {
            ulonglong2 v0 = *(const ulonglong2*)(qp0 + d * 8);
            ulonglong2 v1 = *(const ulonglong2*)(qp1 + d * 8);
            qa[2 * d] = v0.x; qa[2 * d + 1] = v0.y;
            qb[2 * d] = v1.x; qb[2 * d + 1] = v1.y;
        }
    }

    // stage full slice (2048 float4, 16 per thread)
    {
        const float4* src =
            (const float4*)(kh + ((size_t)b * L_ + sl * SLK) * 64);
        float4* dst = (float4*)Ks;
#pragma unroll
        for (int j = 0; j < 16; j++)
            dst[tid + j * 128] = src[tid + j * 128];
    }
    __syncthreads();

    float sa[4] = {0.0f, 0.0f, 0.0f, 0.0f};
    float sb[4] = {0.0f, 0.0f, 0.0f, 0.0f};

#pragma unroll 2
    for (int m = 0; m < SLK; m++) {
        const float* krow = Ks + m * 64 + hh * 4;
        u64t a0, a1, b0, b1;
        {
            ulonglong2 kd = *(const ulonglong2*)krow;
            a0 = mul2(qa[0], kd.x); a1 = mul2(qa[1], kd.y);
            b0 = mul2(qb[0], kd.x); b1 = mul2(qb[1], kd.y);
        }
#pragma unroll
        for (int d = 1; d < 8; d++) {
            ulonglong2 kd = *(const ulonglong2*)(krow + d * 8);
            a0 = fma2(qa[2 * d],     kd.x, a0);
            a1 = fma2(qa[2 * d + 1], kd.y, a1);
            b0 = fma2(qb[2 * d],     kd.x, b0);
            b1 = fma2(qb[2 * d + 1], kd.y, b1);
        }
        float lo, hi;
        unpack2(a0, lo, hi); sa[0] += ex2f(lo); sa[1] += ex2f(hi);
        unpack2(a1, lo, hi); sa[2] += ex2f(lo); sa[3] += ex2f(hi);
        unpack2(b0, lo, hi); sb[0] += ex2f(lo); sb[1] += ex2f(hi);
        unpack2(b1, lo, hi); sb[2] += ex2f(lo); sb[3] += ex2f(hi);
    }

    ((float4*)(part + qi0 * (NSL * 8) + sl * 8 + hh * 4))[0] =
        make_float4(sa[0], sa[1], sa[2], sa[3]);
    ((float4*)(part + qi1 * (NSL * 8) + sl * 8 + hh * 4))[0] =
        make_float4(sb[0], sb[1], sb[2], sb[3]);
}

// ---------------------------------------------------------------------------
// Attention pass 2: per-slice NORMALIZED ctx partials + fp32 attn_wts.
// warp = qg*2 + hh; lane owns one query, 4 heads. li = -log2(denom) folded
// into QK accumulator init => ex2 yields normalized p. 64-key K+V tiles.
// Head-half combine for attn_wts per warp-PAIR with 64-thread named barriers.
// ---------------------------------------------------------------------------
__global__ __launch_bounds__(256) void attn_pass2(
    const float* __restrict__ qh, const float* __restrict__ kh,
    const float* __restrict__ vh, const float* __restrict__ part,
    float* __restrict__ ctxp, float* __restrict__ attn_out)
{
    __shared__ float Ks[64 * 64];          // 16KB
    __shared__ float Vs[64 * 64];          // 16KB
    __shared__ float Wtile[8][32][17];     // 17.4KB

    const int b    = blockIdx.z;
    const int sl   = blockIdx.y;
    const int tid  = threadIdx.x;
    const int warp = tid >> 5;
    const int lane = tid & 31;
    const int qg   = warp >> 1;
    const int hh   = warp & 1;
    const int lt   = tid & 63;             // id within warp-pair
    const size_t qi = (size_t)b * L_ + blockIdx.x * 128 + qg * 32 + lane;

    u64t q2[16];
    {
        const float* qp = qh + qi * 64 + hh * 4;
#pragma unroll
        for (int d = 0; d < 8; d++) {
            ulonglong2 v = *(const ulonglong2*)(qp + d * 8);
            q2[2 * d] = v.x; q2[2 * d + 1] = v.y;
        }
    }

    // li2 = -log2(total denominator) for this half's 4 heads
    u64t li2[2];
    {
        float s[4] = {0.0f, 0.0f, 0.0f, 0.0f};
        const float4* pp = (const float4*)(part + qi * (NSL * 8));
#pragma unroll
        for (int ss = 0; ss < NSL; ss++) {
            float4 a = pp[2 * ss + hh];
            s[0] += a.x; s[1] += a.y; s[2] += a.z; s[3] += a.w;
        }
        li2[0] = pack2(-lg2f(s[0]), -lg2f(s[1]));
        li2[1] = pack2(-lg2f(s[2]), -lg2f(s[3]));
    }

    u64t ctx2[16];
#pragma unroll
    for (int j = 0; j < 16; j++) ctx2[j] = 0ull;

    for (int t = 0; t < SLK / 64; t++) {
        __syncthreads();
        {
            const size_t rowb = ((size_t)b * L_ + sl * SLK + t * 64) * 16;
            const float4* ksrc = (const float4*)kh + rowb;
            const float4* vsrc = (const float4*)vh + rowb;
            float4* kdst = (float4*)Ks;
            float4* vdst = (float4*)Vs;
#pragma unroll
            for (int j = 0; j < 4; j++) {
                kdst[tid + j * 256] = ksrc[tid + j * 256];
                vdst[tid + j * 256] = vsrc[tid + j * 256];
            }
        }
        __syncthreads();

        for (int chunk = 0; chunk < 4; chunk++) {
#pragma unroll 2
            for (int mm = 0; mm < 16; mm++) {
                const int m = chunk * 16 + mm;
                const float* krow = Ks + m * 64 + hh * 4;
                u64t acc0 = li2[0], acc1 = li2[1];
#pragma unroll
                for (int d = 0; d < 8; d++) {
                    ulonglong2 kd = *(const ulonglong2*)(krow + d * 8);
                    acc0 = fma2(q2[2 * d],     kd.x, acc0);
                    acc1 = fma2(q2[2 * d + 1], kd.y, acc1);
                }
                float e0, e1, e2v, e3v;
                { float lo, hi; unpack2(acc0, lo, hi); e0 = ex2f(lo); e1 = ex2f(hi); }
                { float lo, hi; unpack2(acc1, lo, hi); e2v = ex2f(lo); e3v = ex2f(hi); }
                Wtile[warp][lane][mm] = (e0 + e1) + (e2v + e3v);

                u64t ep0 = pack2(e0, e1), ep1 = pack2(e2v, e3v);
                const float* vrow = Vs + m * 64 + hh * 4;
#pragma unroll
                for (int d = 0; d < 8; d++) {
                    ulonglong2 vd = *(const ulonglong2*)(vrow + d * 8);
                    ctx2[2 * d]     = fma2(ep0, vd.x, ctx2[2 * d]);
                    ctx2[2 * d + 1] = fma2(ep1, vd.y, ctx2[2 * d + 1]);
                }
            }
            // pair-combine hh halves -> fp32 attn_out (64-thread barrier)
            barpair(1 + qg);
            {
                const int m0 = sl * SLK + t * 64 + chunk * 16;
                const size_t row0 = (size_t)b * L_ + blockIdx.x * 128 + qg * 32;
#pragma unroll
                for (int it = 0; it < 8; it++) {
                    int idx = lt + it * 64;             // 0..511
                    int c   = idx & 15;
                    int r   = idx >> 4;                 // 0..31
                    float w = (Wtile[qg * 2][r][c] + Wtile[qg * 2 + 1][r][c])
                              * 0.125f;
                    attn_out[(row0 + r) * L_ + m0 + c] = w;
                }
            }
            barpair(1 + qg);
        }
    }

    // store this half's normalized ctx partial (disjoint 16B chunks)
    float* cb = ctxp + (size_t)sl * ROWS * 64 + qi * 64 + hh * 4;
#pragma unroll
    for (int d = 0; d < 8; d++) {
        ulonglong2 v;
        v.x = ctx2[2 * d]; v.y = ctx2[2 * d + 1];
        *(ulonglong2*)(cb + d * 8) = v;
    }
}

// ---------------------------------------------------------------------------
extern "C" void kernel_launch(void* const* d_in, const int* in_sizes, int n_in,
                              void* d_out, int out_size)
{
    const float* q    = (const float*)d_in[0];
    const float* k    = (const float*)d_in[1];
    const float* prev = (const float*)d_in[2];
    const float* Wq   = (const float*)d_in[3];
    const float* bq   = (const float*)d_in[4];
    const float* Wk   = (const float*)d_in[5];
    const float* bk   = (const float*)d_in[6];
    const float* Wv   = (const float*)d_in[7];
    const float* bv   = (const float*)d_in[8];
    const float* Wo   = (const float*)d_in[9];
    const float* bo   = (const float*)d_in[10];
    const float* g1   = (const float*)d_in[11];
    const float* be1  = (const float*)d_in[12];
    const float* W1   = (const float*)d_in[13];
    const float* b1   = (const float*)d_in[14];
    const float* W2   = (const float*)d_in[15];
    const float* b2   = (const float*)d_in[16];
    const float* g2   = (const float*)d_in[17];
    const float* be2  = (const float*)d_in[18];

    float* outp = (float*)d_out;                    // [B, Lq, E]
    float* attn = outp + (size_t)ROWS * E_;         // [B, Lq, Lk]

    float *qh, *khp, *vhp, *xbuf, *f1, *p1, *ctxp;
    cudaGetSymbolAddress((void**)&qh,  g_qh);
    cudaGetSymbolAddress((void**)&khp, g_kh);
    cudaGetSymbolAddress((void**)&vhp, g_vh);
    cudaGetSymbolAddress((void**)&xbuf,g_x);
    cudaGetSymbolAddress((void**)&f1,  g_f1);
    cudaGetSymbolAddress((void**)&p1,  g_p1);
    cudaGetSymbolAddress((void**)&ctxp,g_ctxp);

    const int GB = ROWS / 32;   // 1024 blocks per gemm (single wave)
    // projections into [d*8+h] layout; q pre-scaled by QK_SCALE*log2(e)
    gemm64<<<GB, 128>>>(q, Wq, bq, qh,  QK_SCALE * LOG2E_F, 0, 1);
    gemm64<<<GB, 128>>>(k, Wk, bk, khp, 1.0f, 0, 1);
    gemm64<<<GB, 128>>>(k, Wv, bv, vhp, 1.0f, 0, 1);

    attn_pass1<<<dim3(L_ / 128, NSL, B_), 128>>>(qh, khp, p1);
    attn_pass2<<<dim3(L_ / 128, NSL, B_), 256>>>(qh, khp, vhp, p1, ctxp, attn);

    // Wo GEMM + ctx_combine (nsl_sum) + residual(prev) + LN1  -> xbuf
    gemm_ln<<<GB, 128>>>(ctxp, Wo, bo, prev, g1, be1, xbuf, 1, 1);

    // FFN
    gemm64<<<GB, 128>>>(xbuf, W1, b1, f1, 1.0f, 1, 0);
    // W2 GEMM + residual(xbuf) + LN2 -> final out
    gemm_ln<<<GB, 128>>>(f1, W2, b2, xbuf, g2, be2, outp, 0, 0);
}

// round 11
// speedup vs baseline: 1.4379x; 1.0218x over previous
#include <cuda_runtime.h>
#include <math.h>

#define B_ 64
#define L_ 512
#define E_ 64
#define H_ 8
#define D_ 8
#define ROWS (B_*L_)          // 32768
#define QK_SCALE 0.35355339059327373f   // 1/sqrt(8)
#define LOG2E_F  1.4426950408889634f
#define NSL 4                 // key slices
#define SLK (L_/NSL)          // 128 keys per slice

typedef unsigned long long u64t;

// ---- packed f32x2 helpers (ptxas never auto-fuses; PTX only) ----
__device__ __forceinline__ u64t fma2(u64t a, u64t b, u64t c) {
    u64t d; asm("fma.rn.f32x2 %0, %1, %2, %3;" : "=l"(d) : "l"(a), "l"(b), "l"(c)); return d;
}
__device__ __forceinline__ u64t mul2(u64t a, u64t b) {
    u64t d; asm("mul.rn.f32x2 %0, %1, %2;" : "=l"(d) : "l"(a), "l"(b)); return d;
}
__device__ __forceinline__ u64t pack2(float lo, float hi) {
    u64t d; asm("mov.b64 %0, {%1, %2};" : "=l"(d) : "f"(lo), "f"(hi)); return d;
}
__device__ __forceinline__ void unpack2(u64t a, float& lo, float& hi) {
    asm("mov.b64 {%0, %1}, %2;" : "=f"(lo), "=f"(hi) : "l"(a));
}
__device__ __forceinline__ float ex2f(float x) {
    float r; asm("ex2.approx.f32 %0, %1;" : "=f"(r) : "f"(x)); return r;
}
__device__ __forceinline__ float lg2f(float x) {
    float r; asm("lg2.approx.f32 %0, %1;" : "=f"(r) : "f"(x)); return r;
}
__device__ __forceinline__ void barpair(int id) {
    asm volatile("bar.sync %0, 64;" :: "r"(id) : "memory");
}

// ---- scratch (static device arrays; no allocation) ----
__device__ float g_qh  [ROWS*E_];
__device__ float g_kh  [ROWS*E_];
__device__ float g_vh  [ROWS*E_];
__device__ float g_x   [ROWS*E_];
__device__ float g_f1  [ROWS*E_];
__device__ float g_p1  [ROWS*NSL*H_];     // per-slice denominator partials
__device__ float g_ctxp[NSL*ROWS*E_];     // per-slice ctx partials (32MB)

// ---------------------------------------------------------------------------
// GEMM compute core: xs[32][68], Ws[64][68] staged; 4x4 tile per thread,
// LDS.128 j-quad inner loop, packed fma2, 32-reg accumulators.
// ---------------------------------------------------------------------------
__device__ __forceinline__ void gemm_core(
    const float (*xs)[68], const float (*Ws)[68], int tx, int ty,
    u64t acc2[4][4])
{
#pragma unroll
    for (int rr = 0; rr < 4; rr++)
#pragma unroll
        for (int c = 0; c < 4; c++) acc2[rr][c] = 0ull;

#pragma unroll 4
    for (int j4 = 0; j4 < 16; j4++) {
        ulonglong2 xv[4], wv[4];
#pragma unroll
        for (int rr = 0; rr < 4; rr++)
            xv[rr] = *(const ulonglong2*)&xs[ty * 4 + rr][4 * j4];
#pragma unroll
        for (int c = 0; c < 4; c++)
            wv[c] = *(const ulonglong2*)&Ws[tx + c * 16][4 * j4];
#pragma unroll
        for (int rr = 0; rr < 4; rr++)
#pragma unroll
            for (int c = 0; c < 4; c++) {
                acc2[rr][c] = fma2(xv[rr].x, wv[c].x, acc2[rr][c]);
                acc2[rr][c] = fma2(xv[rr].y, wv[c].y, acc2[rr][c]);
            }
    }
}

// ---------------------------------------------------------------------------
// Fused q/k/v projection: blockIdx.y picks (X, W, bias, out, scale).
// Output in [d*8+h] attn layout; q pre-scaled by QK_SCALE*log2(e).
// 32 rows / 128 threads; 3072 blocks in ONE launch.
// ---------------------------------------------------------------------------
__global__ __launch_bounds__(128) void proj3(
    const float* __restrict__ q, const float* __restrict__ k,
    const float* __restrict__ Wq, const float* __restrict__ bq,
    const float* __restrict__ Wk, const float* __restrict__ bk,
    const float* __restrict__ Wv, const float* __restrict__ bv,
    float* __restrict__ qh, float* __restrict__ kh, float* __restrict__ vh)
{
    __shared__ float xs[32][68];
    __shared__ float Ws[64][68];

    const int t = threadIdx.x;
    const int which = blockIdx.y;
    const int rowbase = blockIdx.x * 32;

    const float* X    = (which == 0) ? q  : k;
    const float* W    = (which == 0) ? Wq : (which == 1) ? Wk : Wv;
    const float* bias = (which == 0) ? bq : (which == 1) ? bk : bv;
    float* Y          = (which == 0) ? qh : (which == 1) ? kh : vh;
    const float scale = (which == 0) ? QK_SCALE * LOG2E_F : 1.0f;

    // vectorized staging: X 512 float4s (4/thread), W 1024 float4s (8/thread)
#pragma unroll
    for (int j = 0; j < 4; j++) {
        int fidx = t + j * 128;                  // 0..511
        int r = fidx >> 4, c = (fidx & 15) * 4;
        *(float4*)&xs[r][c] = ((const float4*)(X + (size_t)rowbase * 64))[fidx];
    }
#pragma unroll
    for (int j = 0; j < 8; j++) {
        int fidx = t + j * 128;                  // 0..1023
        int r = fidx >> 4, c = (fidx & 15) * 4;
        *(float4*)&Ws[r][c] = ((const float4*)W)[fidx];
    }
    __syncthreads();

    const int tx = t & 15;
    const int ty = t >> 4;
    u64t acc2[4][4];
    gemm_core(xs, Ws, tx, ty, acc2);

#pragma unroll
    for (int c = 0; c < 4; c++) {
        int col = tx + c * 16;
        float bb = bias[col];
        int ocol = (col & 7) * 8 + (col >> 3);   // dh transpose
#pragma unroll
        for (int rr = 0; rr < 4; rr++) {
            float lo, hi; unpack2(acc2[rr][c], lo, hi);
            Y[(size_t)(rowbase + ty * 4 + rr) * 64 + ocol] =
                scale * ((lo + hi) + bb);
        }
    }
}

// ---------------------------------------------------------------------------
// Plain 64-wide GEMM (FFN W1, relu): 32 rows / 128 threads / 1024 blocks.
// ---------------------------------------------------------------------------
__global__ __launch_bounds__(128) void gemm64(
    const float* __restrict__ X, const float* __restrict__ W,
    const float* __restrict__ bias, float* __restrict__ Y, int relu)
{
    __shared__ float xs[32][68];
    __shared__ float Ws[64][68];

    const int t = threadIdx.x;
    const int rowbase = blockIdx.x * 32;

#pragma unroll
    for (int j = 0; j < 4; j++) {
        int fidx = t + j * 128;
        int r = fidx >> 4, c = (fidx & 15) * 4;
        *(float4*)&xs[r][c] = ((const float4*)(X + (size_t)rowbase * 64))[fidx];
    }
#pragma unroll
    for (int j = 0; j < 8; j++) {
        int fidx = t + j * 128;
        int r = fidx >> 4, c = (fidx & 15) * 4;
        *(float4*)&Ws[r][c] = ((const float4*)W)[fidx];
    }
    __syncthreads();

    const int tx = t & 15;
    const int ty = t >> 4;
    u64t acc2[4][4];
    gemm_core(xs, Ws, tx, ty, acc2);

#pragma unroll
    for (int c = 0; c < 4; c++) {
        int col = tx + c * 16;
        float bb = bias[col];
#pragma unroll
        for (int rr = 0; rr < 4; rr++) {
            float lo, hi; unpack2(acc2[rr][c], lo, hi);
            float v = (lo + hi) + bb;
            if (relu) v = fmaxf(v, 0.0f);
            Y[(size_t)(rowbase + ty * 4 + rr) * 64 + col] = v;
        }
    }
}

// ---------------------------------------------------------------------------
// Fused GEMM + residual add + LayerNorm (for Wo/ln1 and W2/ln2).
// out[r] = LN( X@W^T + bias + resid[r] )
// nsl_sum: X points at ctxp; stage xs as the sum of the NSL slice partials
//          (fuses ctx_combine). wperm: permute W's j index ([d*8+h] inputs).
// ---------------------------------------------------------------------------
__global__ __launch_bounds__(128) void gemm_ln(
    const float* __restrict__ X, const float* __restrict__ W,
    const float* __restrict__ bias, const float* __restrict__ resid,
    const float* __restrict__ g, const float* __restrict__ beta,
    float* __restrict__ out, int wperm, int nsl_sum)
{
    __shared__ float xs[32][68];
    __shared__ float Ws[64][68];
    __shared__ float red[32][8];

    const int t = threadIdx.x;
    const int rowbase = blockIdx.x * 32;

    if (nsl_sum) {
#pragma unroll
        for (int j = 0; j < 4; j++) {
            int fidx = t + j * 128;                  // 0..511 float4s
            size_t gf = (size_t)rowbase * 16 + fidx;
            float4 s = ((const float4*)X)[gf];
#pragma unroll
            for (int ss = 1; ss < NSL; ss++) {
                float4 a = ((const float4*)X)[(size_t)ss * ROWS * 16 + gf];
                s.x += a.x; s.y += a.y; s.z += a.z; s.w += a.w;
            }
            int r = fidx >> 4, c = (fidx & 15) * 4;
            *(float4*)&xs[r][c] = s;
        }
    } else {
#pragma unroll
        for (int j = 0; j < 4; j++) {
            int fidx = t + j * 128;
            int r = fidx >> 4, c = (fidx & 15) * 4;
            *(float4*)&xs[r][c] =
                ((const float4*)(X + (size_t)rowbase * 64))[fidx];
        }
    }
    if (wperm) {
#pragma unroll
        for (int kk = 0; kk < 32; kk++) {            // scalar gather
            int idx = t + kk * 128;
            int r = idx >> 6, c = idx & 63;
            int cc = (c & 7) * 8 + (c >> 3);
            Ws[r][c] = W[r * 64 + cc];
        }
    } else {
#pragma unroll
        for (int j = 0; j < 8; j++) {
            int fidx = t + j * 128;
            int r = fidx >> 4, c = (fidx & 15) * 4;
            *(float4*)&Ws[r][c] = ((const float4*)W)[fidx];
        }
    }
    __syncthreads();

    const int tx = t & 15;
    const int ty = t >> 4;
    u64t acc2[4][4];
    gemm_core(xs, Ws, tx, ty, acc2);

    __syncthreads();   // done reading xs; reuse it for the pre-LN values
#pragma unroll
    for (int c = 0; c < 4; c++) {
        int col = tx + c * 16;
        float bb = bias[col];
#pragma unroll
        for (int rr = 0; rr < 4; rr++) {
            float lo, hi; unpack2(acc2[rr][c], lo, hi);
            int row = ty * 4 + rr;
            xs[row][col] = (lo + hi) + bb +
                           resid[(size_t)(rowbase + row) * 64 + col];
        }
    }
    __syncthreads();

    // LN over each row of 64: 4 threads per row, 16 cols each
    const int row  = t >> 2;
    const int part = t & 3;
    float lsum = 0.0f, lsq = 0.0f;
#pragma unroll
    for (int j = 0; j < 16; j++) {
        float v = xs[row][part * 16 + j];
        lsum += v;
        lsq  = fmaf(v, v, lsq);
    }
    red[row][part]     = lsum;
    red[row][part + 4] = lsq;
    __syncthreads();

    float s  = red[row][0] + red[row][1] + red[row][2] + red[row][3];
    float sq = red[row][4] + red[row][5] + red[row][6] + red[row][7];
    float mu   = s * (1.0f / 64.0f);
    float var  = sq * (1.0f / 64.0f) - mu * mu;
    float rstd = rsqrtf(var + 1e-5f);

    float4 o[4];
#pragma unroll
    for (int j = 0; j < 16; j++) {
        int c = part * 16 + j;
        ((float*)o)[j] = fmaf((xs[row][c] - mu) * rstd, g[c], beta[c]);
    }
    float4* op = (float4*)(out + (size_t)(rowbase + row) * 64 + part * 16);
#pragma unroll
    for (int j = 0; j < 4; j++) op[j] = o[j];
}

// ---------------------------------------------------------------------------
// Attention pass 1: per-slice softmax denominator partials.
// Block 128 thr = 4 warps: warp = qg*2 + hh. Lane owns TWO queries, 4 heads.
// Whole 128-key slice staged once (32KB). Grid (L/128, NSL, B).
// ---------------------------------------------------------------------------
__global__ __launch_bounds__(128) void attn_pass1(
    const float* __restrict__ qh, const float* __restrict__ kh,
    float* __restrict__ part)
{
    __shared__ float Ks[SLK * 64];   // 32KB

    const int b    = blockIdx.z;
    const int sl   = blockIdx.y;
    const int tid  = threadIdx.x;
    const int warp = tid >> 5;
    const int lane = tid & 31;
    const int qg   = warp >> 1;
    const int hh   = warp & 1;
    const size_t qi0 = (size_t)b * L_ + blockIdx.x * 128 + qg * 64 + lane;
    const size_t qi1 = qi0 + 32;

    u64t qa[16], qb[16];
    {
        const float* qp0 = qh + qi0 * 64 + hh * 4;
        const float* qp1 = qh + qi1 * 64 + hh * 4;
#pragma unroll
        for (int d = 0; d < 8; d++) {
            ulonglong2 v0 = *(const ulonglong2*)(qp0 + d * 8);
            ulonglong2 v1 = *(const ulonglong2*)(qp1 + d * 8);
            qa[2 * d] = v0.x; qa[2 * d + 1] = v0.y;
            qb[2 * d] = v1.x; qb[2 * d + 1] = v1.y;
        }
    }

    {
        const float4* src =
            (const float4*)(kh + ((size_t)b * L_ + sl * SLK) * 64);
        float4* dst = (float4*)Ks;
#pragma unroll
        for (int j = 0; j < 16; j++)
            dst[tid + j * 128] = src[tid + j * 128];
    }
    __syncthreads();

    float sa[4] = {0.0f, 0.0f, 0.0f, 0.0f};
    float sb[4] = {0.0f, 0.0f, 0.0f, 0.0f};

#pragma unroll 2
    for (int m = 0; m < SLK; m++) {
        const float* krow = Ks + m * 64 + hh * 4;
        u64t a0, a1, b0, b1;
        {
            ulonglong2 kd = *(const ulonglong2*)krow;
            a0 = mul2(qa[0], kd.x); a1 = mul2(qa[1], kd.y);
            b0 = mul2(qb[0], kd.x); b1 = mul2(qb[1], kd.y);
        }
#pragma unroll
        for (int d = 1; d < 8; d++) {
            ulonglong2 kd = *(const ulonglong2*)(krow + d * 8);
            a0 = fma2(qa[2 * d],     kd.x, a0);
            a1 = fma2(qa[2 * d + 1], kd.y, a1);
            b0 = fma2(qb[2 * d],     kd.x, b0);
            b1 = fma2(qb[2 * d + 1], kd.y, b1);
        }
        float lo, hi;
        unpack2(a0, lo, hi); sa[0] += ex2f(lo); sa[1] += ex2f(hi);
        unpack2(a1, lo, hi); sa[2] += ex2f(lo); sa[3] += ex2f(hi);
        unpack2(b0, lo, hi); sb[0] += ex2f(lo); sb[1] += ex2f(hi);
        unpack2(b1, lo, hi); sb[2] += ex2f(lo); sb[3] += ex2f(hi);
    }

    ((float4*)(part + qi0 * (NSL * 8) + sl * 8 + hh * 4))[0] =
        make_float4(sa[0], sa[1], sa[2], sa[3]);
    ((float4*)(part + qi1 * (NSL * 8) + sl * 8 + hh * 4))[0] =
        make_float4(sb[0], sb[1], sb[2], sb[3]);
}

// ---------------------------------------------------------------------------
// Attention pass 2: per-slice NORMALIZED ctx partials + fp32 attn_wts.
// warp = qg*2 + hh; lane owns one query, 4 heads. li = -log2(denom) folded
// into QK accumulator init => ex2 yields normalized p. 64-key K+V tiles.
// Head-half combine for attn_wts per warp-PAIR with 64-thread named barriers.
// ---------------------------------------------------------------------------
__global__ __launch_bounds__(256) void attn_pass2(
    const float* __restrict__ qh, const float* __restrict__ kh,
    const float* __restrict__ vh, const float* __restrict__ part,
    float* __restrict__ ctxp, float* __restrict__ attn_out)
{
    __shared__ float Ks[64 * 64];          // 16KB
    __shared__ float Vs[64 * 64];          // 16KB
    __shared__ float Wtile[8][32][17];     // 17.4KB

    const int b    = blockIdx.z;
    const int sl   = blockIdx.y;
    const int tid  = threadIdx.x;
    const int warp = tid >> 5;
    const int lane = tid & 31;
    const int qg   = warp >> 1;
    const int hh   = warp & 1;
    const int lt   = tid & 63;             // id within warp-pair
    const size_t qi = (size_t)b * L_ + blockIdx.x * 128 + qg * 32 + lane;

    u64t q2[16];
    {
        const float* qp = qh + qi * 64 + hh * 4;
#pragma unroll
        for (int d = 0; d < 8; d++) {
            ulonglong2 v = *(const ulonglong2*)(qp + d * 8);
            q2[2 * d] = v.x; q2[2 * d + 1] = v.y;
        }
    }

    u64t li2[2];
    {
        float s[4] = {0.0f, 0.0f, 0.0f, 0.0f};
        const float4* pp = (const float4*)(part + qi * (NSL * 8));
#pragma unroll
        for (int ss = 0; ss < NSL; ss++) {
            float4 a = pp[2 * ss + hh];
            s[0] += a.x; s[1] += a.y; s[2] += a.z; s[3] += a.w;
        }
        li2[0] = pack2(-lg2f(s[0]), -lg2f(s[1]));
        li2[1] = pack2(-lg2f(s[2]), -lg2f(s[3]));
    }

    u64t ctx2[16];
#pragma unroll
    for (int j = 0; j < 16; j++) ctx2[j] = 0ull;

    for (int t = 0; t < SLK / 64; t++) {
        __syncthreads();
        {
            const size_t rowb = ((size_t)b * L_ + sl * SLK + t * 64) * 16;
            const float4* ksrc = (const float4*)kh + rowb;
            const float4* vsrc = (const float4*)vh + rowb;
            float4* kdst = (float4*)Ks;
            float4* vdst = (float4*)Vs;
#pragma unroll
            for (int j = 0; j < 4; j++) {
                kdst[tid + j * 256] = ksrc[tid + j * 256];
                vdst[tid + j * 256] = vsrc[tid + j * 256];
            }
        }
        __syncthreads();

        for (int chunk = 0; chunk < 4; chunk++) {
#pragma unroll 2
            for (int mm = 0; mm < 16; mm++) {
                const int m = chunk * 16 + mm;
                const float* krow = Ks + m * 64 + hh * 4;
                u64t acc0 = li2[0], acc1 = li2[1];
#pragma unroll
                for (int d = 0; d < 8; d++) {
                    ulonglong2 kd = *(const ulonglong2*)(krow + d * 8);
                    acc0 = fma2(q2[2 * d],     kd.x, acc0);
                    acc1 = fma2(q2[2 * d + 1], kd.y, acc1);
                }
                float e0, e1, e2v, e3v;
                { float lo, hi; unpack2(acc0, lo, hi); e0 = ex2f(lo); e1 = ex2f(hi); }
                { float lo, hi; unpack2(acc1, lo, hi); e2v = ex2f(lo); e3v = ex2f(hi); }
                Wtile[warp][lane][mm] = (e0 + e1) + (e2v + e3v);

                u64t ep0 = pack2(e0, e1), ep1 = pack2(e2v, e3v);
                const float* vrow = Vs + m * 64 + hh * 4;
#pragma unroll
                for (int d = 0; d < 8; d++) {
                    ulonglong2 vd = *(const ulonglong2*)(vrow + d * 8);
                    ctx2[2 * d]     = fma2(ep0, vd.x, ctx2[2 * d]);
                    ctx2[2 * d + 1] = fma2(ep1, vd.y, ctx2[2 * d + 1]);
                }
            }
            // pair-combine hh halves -> fp32 attn_out (64-thread barrier)
            barpair(1 + qg);
            {
                const int m0 = sl * SLK + t * 64 + chunk * 16;
                const size_t row0 = (size_t)b * L_ + blockIdx.x * 128 + qg * 32;
#pragma unroll
                for (int it = 0; it < 8; it++) {
                    int idx = lt + it * 64;             // 0..511
                    int c   = idx & 15;
                    int r   = idx >> 4;                 // 0..31
                    float w = (Wtile[qg * 2][r][c] + Wtile[qg * 2 + 1][r][c])
                              * 0.125f;
                    attn_out[(row0 + r) * L_ + m0 + c] = w;
                }
            }
            barpair(1 + qg);
        }
    }

    // store this half's normalized ctx partial (disjoint 16B chunks)
    float* cb = ctxp + (size_t)sl * ROWS * 64 + qi * 64 + hh * 4;
#pragma unroll
    for (int d = 0; d < 8; d++) {
        ulonglong2 v;
        v.x = ctx2[2 * d]; v.y = ctx2[2 * d + 1];
        *(ulonglong2*)(cb + d * 8) = v;
    }
}

// ---------------------------------------------------------------------------
extern "C" void kernel_launch(void* const* d_in, const int* in_sizes, int n_in,
                              void* d_out, int out_size)
{
    const float* q    = (const float*)d_in[0];
    const float* k    = (const float*)d_in[1];
    const float* prev = (const float*)d_in[2];
    const float* Wq   = (const float*)d_in[3];
    const float* bq   = (const float*)d_in[4];
    const float* Wk   = (const float*)d_in[5];
    const float* bk   = (const float*)d_in[6];
    const float* Wv   = (const float*)d_in[7];
    const float* bv   = (const float*)d_in[8];
    const float* Wo   = (const float*)d_in[9];
    const float* bo   = (const float*)d_in[10];
    const float* g1   = (const float*)d_in[11];
    const float* be1  = (const float*)d_in[12];
    const float* W1   = (const float*)d_in[13];
    const float* b1   = (const float*)d_in[14];
    const float* W2   = (const float*)d_in[15];
    const float* b2   = (const float*)d_in[16];
    const float* g2   = (const float*)d_in[17];
    const float* be2  = (const float*)d_in[18];

    float* outp = (float*)d_out;                    // [B, Lq, E]
    float* attn = outp + (size_t)ROWS * E_;         // [B, Lq, Lk]

    float *qh, *khp, *vhp, *xbuf, *f1, *p1, *ctxp;
    cudaGetSymbolAddress((void**)&qh,  g_qh);
    cudaGetSymbolAddress((void**)&khp, g_kh);
    cudaGetSymbolAddress((void**)&vhp, g_vh);
    cudaGetSymbolAddress((void**)&xbuf,g_x);
    cudaGetSymbolAddress((void**)&f1,  g_f1);
    cudaGetSymbolAddress((void**)&p1,  g_p1);
    cudaGetSymbolAddress((void**)&ctxp,g_ctxp);

    const int GB = ROWS / 32;   // 1024 blocks per gemm

    // fused q/k/v projections (one launch, 3072 blocks)
    proj3<<<dim3(GB, 3), 128>>>(q, k, Wq, bq, Wk, bk, Wv, bv, qh, khp, vhp);

    attn_pass1<<<dim3(L_ / 128, NSL, B_), 128>>>(qh, khp, p1);
    attn_pass2<<<dim3(L_ / 128, NSL, B_), 256>>>(qh, khp, vhp, p1, ctxp, attn);

    // Wo GEMM + ctx_combine (nsl_sum) + residual(prev) + LN1  -> xbuf
    gemm_ln<<<GB, 128>>>(ctxp, Wo, bo, prev, g1, be1, xbuf, 1, 1);

    // FFN
    gemm64<<<GB, 128>>>(xbuf, W1, b1, f1, 1);
    // W2 GEMM + residual(xbuf) + LN2 -> final out
    gemm_ln<<<GB, 128>>>(f1, W2, b2, xbuf, g2, be2, outp, 0, 0);
}